// round 4
// baseline (speedup 1.0000x reference)
#include <cuda_runtime.h>
#include <cstdint>

#define N_PTS 32768
#define M_PTS 8192
#define CIN   64
#define COUT  128
#define KNN_K 16

#define FPS_CTAS    8
#define FPS_THREADS 1024
#define FPS_PPT     4      // 8*1024*4 = 32768
#define FULLMASK    0xffffffffu

// ---------------- scratch (device globals; no allocation allowed) ----------------
__device__ int   g_fps_idx[M_PTS];
__device__ int   g_nbr[M_PTS * KNN_K];
__device__ float g_h[N_PTS * COUT];      // relu(xW+b), 16 MB
// binning scratch
__device__ int   g_cellcnt[4096];
__device__ int   g_celloff[4096];
__device__ float g_bx[N_PTS], g_by[N_PTS], g_bz[N_PTS];
__device__ int   g_bidx[N_PTS];

// strict non-FMA fp32 distance: matches XLA mul -> reduce-add (rel_err==0 verified)
__device__ __forceinline__ float dist2s(float x, float y, float z,
                                        float px, float py, float pz) {
    float dx = __fsub_rn(x, px);
    float dy = __fsub_rn(y, py);
    float dz = __fsub_rn(z, pz);
    return __fadd_rn(__fadd_rn(__fmul_rn(dx, dx), __fmul_rn(dy, dy)), __fmul_rn(dz, dz));
}

// ---------------- binning: 16^3 Morton grid ----------------
__device__ __forceinline__ int expand3(int v) {
    return (v & 1) | ((v & 2) << 2) | ((v & 4) << 4) | ((v & 8) << 6);
}
__device__ __forceinline__ int cell_of(float x, float y, float z) {
    int cx = min(15, max(0, (int)floorf((x + 4.0f) * 2.0f)));
    int cy = min(15, max(0, (int)floorf((y + 4.0f) * 2.0f)));
    int cz = min(15, max(0, (int)floorf((z + 4.0f) * 2.0f)));
    return expand3(cx) | (expand3(cy) << 1) | (expand3(cz) << 2);
}

__global__ void zero_kernel() {
    int i = blockIdx.x * blockDim.x + threadIdx.x;
    if (i < 4096) g_cellcnt[i] = 0;
}

__global__ void hist_kernel(const float* __restrict__ pos) {
    int i = blockIdx.x * blockDim.x + threadIdx.x;
    if (i < N_PTS)
        atomicAdd(&g_cellcnt[cell_of(pos[i*3], pos[i*3+1], pos[i*3+2])], 1);
}

__global__ void __launch_bounds__(1024) scan_kernel() {
    __shared__ int s_w[32];
    const int tid = threadIdx.x, lane = tid & 31, w = tid >> 5;
    int v0 = g_cellcnt[tid*4+0], v1 = g_cellcnt[tid*4+1];
    int v2 = g_cellcnt[tid*4+2], v3 = g_cellcnt[tid*4+3];
    int local = v0 + v1 + v2 + v3;
    int x = local;
    #pragma unroll
    for (int off = 1; off < 32; off <<= 1) {
        int y = __shfl_up_sync(FULLMASK, x, off);
        if (lane >= off) x += y;
    }
    if (lane == 31) s_w[w] = x;
    __syncthreads();
    if (w == 0) {
        int y = s_w[lane];
        #pragma unroll
        for (int off = 1; off < 32; off <<= 1) {
            int z = __shfl_up_sync(FULLMASK, y, off);
            if (lane >= off) y += z;
        }
        s_w[lane] = y;
    }
    __syncthreads();
    int exc = x - local + (w > 0 ? s_w[w-1] : 0);
    g_celloff[tid*4+0] = exc;
    g_celloff[tid*4+1] = exc + v0;
    g_celloff[tid*4+2] = exc + v0 + v1;
    g_celloff[tid*4+3] = exc + v0 + v1 + v2;
}

__global__ void scatter_kernel(const float* __restrict__ pos) {
    int i = blockIdx.x * blockDim.x + threadIdx.x;
    if (i < N_PTS) {
        float x = pos[i*3], y = pos[i*3+1], z = pos[i*3+2];
        int slot = atomicAdd(&g_celloff[cell_of(x, y, z)], 1);
        g_bx[slot] = x; g_by[slot] = y; g_bz[slot] = z; g_bidx[slot] = i;
    }
}

// ---------------- FPS: barrier-free tagged-dataflow, push-based cluster exchange ----
// All exchanged words are self-tagged 8-byte values, parity double-buffered:
//   key word:   val(32) | inv(15)<<14 | tag(14)      (inv = 32767-idx; max => first idx)
//   coord word: floatbits(32)<<32 | tag
__device__ __forceinline__ unsigned long long spin_cta(uint32_t addr, unsigned tag) {
    unsigned long long v;
    do {
        asm volatile("ld.relaxed.cta.shared::cta.b64 %0, [%1];"
                     : "=l"(v) : "r"(addr) : "memory");
    } while ((unsigned)(v & 0x3FFFull) != tag);
    return v;
}
__device__ __forceinline__ unsigned long long spin_cluster(uint32_t addr, unsigned tag) {
    unsigned long long v;
    do {
        asm volatile("ld.relaxed.cluster.shared::cta.b64 %0, [%1];"
                     : "=l"(v) : "r"(addr) : "memory");
    } while ((unsigned)(v & 0x3FFFull) != tag);
    return v;
}

__global__ void __launch_bounds__(FPS_THREADS, 1) __cluster_dims__(FPS_CTAS, 1, 1)
fps_kernel(const float* __restrict__ pos) {
    __shared__ unsigned long long s_wslot[2][32][4];  // [par][warp][word], 2KB
    __shared__ unsigned long long s_cl[2][FPS_CTAS][4]; // [par][src][word], 512B

    const int tid  = threadIdx.x;
    const int warp = tid >> 5, lane = tid & 31;
    const int cta  = blockIdx.x;
    const int wbase = (cta * 32 + warp) * 128;

    float X[FPS_PPT], Y[FPS_PPT], Z[FPS_PPT], Mn[FPS_PPT];
    unsigned I[FPS_PPT];
    #pragma unroll
    for (int p = 0; p < FPS_PPT; ++p) {
        int j = wbase + lane + p * 32;
        X[p] = g_bx[j]; Y[p] = g_by[j]; Z[p] = g_bz[j];
        I[p] = (unsigned)g_bidx[j];
        Mn[p] = __int_as_float(0x7f800000);
    }

    // warp bbox (one-time)
    float bxmin = fminf(fminf(X[0], X[1]), fminf(X[2], X[3]));
    float bxmax = fmaxf(fmaxf(X[0], X[1]), fmaxf(X[2], X[3]));
    float bymin = fminf(fminf(Y[0], Y[1]), fminf(Y[2], Y[3]));
    float bymax = fmaxf(fmaxf(Y[0], Y[1]), fmaxf(Y[2], Y[3]));
    float bzmin = fminf(fminf(Z[0], Z[1]), fminf(Z[2], Z[3]));
    float bzmax = fmaxf(fmaxf(Z[0], Z[1]), fmaxf(Z[2], Z[3]));
    #pragma unroll
    for (int off = 16; off > 0; off >>= 1) {
        bxmin = fminf(bxmin, __shfl_xor_sync(FULLMASK, bxmin, off));
        bxmax = fmaxf(bxmax, __shfl_xor_sync(FULLMASK, bxmax, off));
        bymin = fminf(bymin, __shfl_xor_sync(FULLMASK, bymin, off));
        bymax = fmaxf(bymax, __shfl_xor_sync(FULLMASK, bymax, off));
        bzmin = fminf(bzmin, __shfl_xor_sync(FULLMASK, bzmin, off));
        bzmax = fmaxf(bzmax, __shfl_xor_sync(FULLMASK, bzmax, off));
    }

    float wval = __int_as_float(0x7f800000);  // warp skip threshold (cached max-mind)
    // cached warp-uniform candidate (valid after first round; round 1 always updates)
    unsigned ckval = 0, ckinv = 0;
    float ccx = 0.f, ccy = 0.f, ccz = 0.f;

    // zero all tagged slots (tag 0 never matches it>=1)
    if (tid < 256) ((unsigned long long*)s_wslot)[tid] = 0ull;
    if (tid < 2 * FPS_CTAS * 4) ((unsigned long long*)s_cl)[tid] = 0ull;

    const uint32_t wslot_addr = (uint32_t)__cvta_generic_to_shared(&s_wslot[0][0][0]);
    const uint32_t cl_addr    = (uint32_t)__cvta_generic_to_shared(&s_cl[0][0][0]);

    // warp0 push address: lane -> peer (lane>>2), word (lane&3), slot src = my cta
    uint32_t push_base = 0;
    if (warp == 0) {
        uint32_t pa;
        asm("mapa.shared::cluster.u32 %0, %1, %2;"
            : "=r"(pa) : "r"(cl_addr), "r"(lane >> 2));
        push_base = pa + (uint32_t)((cta * 4 + (lane & 3)) * 8);
    }

    float px = pos[0], py = pos[1], pz = pos[2];
    if (cta == 0 && tid == 0) g_fps_idx[0] = 0;

    // peers' slots must be zeroed before any push can arrive
    asm volatile("barrier.cluster.arrive.aligned;" ::: "memory");
    asm volatile("barrier.cluster.wait.aligned;"   ::: "memory");

    for (int it = 1; it < M_PTS; ++it) {
        const unsigned tag = (unsigned)it;
        const int par = it & 1;

        // ---- stage A: prune / update / warp argmax ----
        float dxl = fmaxf(0.f, fmaxf(__fsub_rn(bxmin, px), __fsub_rn(px, bxmax)));
        float dyl = fmaxf(0.f, fmaxf(__fsub_rn(bymin, py), __fsub_rn(py, bymax)));
        float dzl = fmaxf(0.f, fmaxf(__fsub_rn(bzmin, pz), __fsub_rn(pz, bzmax)));
        float dlb = __fadd_rn(__fadd_rn(__fmul_rn(dxl, dxl), __fmul_rn(dyl, dyl)),
                              __fmul_rn(dzl, dzl));

        if (dlb < wval) {                       // warp-uniform branch
            #pragma unroll
            for (int p = 0; p < FPS_PPT; ++p)
                Mn[p] = fminf(Mn[p], dist2s(X[p], Y[p], Z[p], px, py, pz));

            float bv = Mn[0]; unsigned bi = I[0];
            float bx = X[0], by = Y[0], bz = Z[0];
            #pragma unroll
            for (int p = 1; p < FPS_PPT; ++p) {
                if (Mn[p] > bv || (Mn[p] == bv && I[p] < bi)) {
                    bv = Mn[p]; bi = I[p]; bx = X[p]; by = Y[p]; bz = Z[p];
                }
            }
            unsigned vb   = __float_as_uint(bv);
            unsigned wmax = __reduce_max_sync(FULLMASK, vb);
            unsigned widx = __reduce_min_sync(FULLMASK, (vb == wmax) ? bi : 0xffffffffu);
            wval  = __uint_as_float(wmax);
            ckval = wmax;
            ckinv = 32767u - widx;
            int wl = __ffs(__ballot_sync(FULLMASK, vb == wmax && bi == widx)) - 1;
            ccx = __shfl_sync(FULLMASK, bx, wl);
            ccy = __shfl_sync(FULLMASK, by, wl);
            ccz = __shfl_sync(FULLMASK, bz, wl);
        }

        // publish warp candidate (every round; cheap re-tag on skip rounds)
        if (lane < 4) {
            unsigned long long w;
            if (lane == 0)
                w = ((unsigned long long)ckval << 32)
                  | ((unsigned long long)ckinv << 14) | tag;
            else {
                float c = (lane == 1) ? ccx : (lane == 2) ? ccy : ccz;
                w = ((unsigned long long)__float_as_uint(c) << 32) | tag;
            }
            uint32_t a = wslot_addr + (uint32_t)(par * 1024 + warp * 32 + lane * 8);
            asm volatile("st.relaxed.cta.shared::cta.b64 [%0], %1;"
                         :: "r"(a), "l"(w) : "memory");
        }

        // ---- stage B (warp0): CTA argmax + push to all 8 CTAs ----
        if (warp == 0) {
            unsigned long long v = spin_cta(
                wslot_addr + (uint32_t)(par * 1024 + lane * 32), tag);
            unsigned val = (unsigned)(v >> 32);
            unsigned inv = (unsigned)((v >> 14) & 0x7FFFull);
            unsigned cmax = __reduce_max_sync(FULLMASK, val);
            unsigned cinv = __reduce_max_sync(FULLMASK, (val == cmax) ? inv : 0u);
            int wl = __ffs(__ballot_sync(FULLMASK, val == cmax && inv == cinv)) - 1;

            unsigned cw = 0;
            if (lane >= 1 && lane <= 3) {
                unsigned long long c = spin_cta(
                    wslot_addr + (uint32_t)(par * 1024 + wl * 32 + lane * 8), tag);
                cw = (unsigned)(c >> 32);
            }
            unsigned cxb = __shfl_sync(FULLMASK, cw, 1);
            unsigned cyb = __shfl_sync(FULLMASK, cw, 2);
            unsigned czb = __shfl_sync(FULLMASK, cw, 3);

            const int word = lane & 3;
            unsigned long long pw;
            if (word == 0)
                pw = ((unsigned long long)cmax << 32)
                   | ((unsigned long long)cinv << 14) | tag;
            else
                pw = ((unsigned long long)(word == 1 ? cxb : word == 2 ? cyb : czb) << 32)
                   | tag;
            asm volatile("st.relaxed.cluster.shared::cluster.b64 [%0], %1;"
                         :: "r"(push_base + (uint32_t)(par * 256)), "l"(pw) : "memory");
        }

        // ---- stage C (all warps): local cluster argmax -> pick ----
        {
            unsigned long long g = spin_cluster(
                cl_addr + (uint32_t)(par * 256 + lane * 8), tag);
            const bool iskey = (lane & 3) == 0;
            unsigned hval = iskey ? (unsigned)(g >> 32) : 0u;
            unsigned hmax = __reduce_max_sync(FULLMASK, hval);
            unsigned ginv = (unsigned)((g >> 14) & 0x7FFFull);
            unsigned hinv = __reduce_max_sync(FULLMASK,
                                (iskey && hval == hmax) ? ginv : 0u);
            int l0 = __ffs(__ballot_sync(FULLMASK,
                        iskey && hval == hmax && ginv == hinv)) - 1;
            unsigned hi = (unsigned)(g >> 32);
            px = __uint_as_float(__shfl_sync(FULLMASK, hi, l0 + 1));
            py = __uint_as_float(__shfl_sync(FULLMASK, hi, l0 + 2));
            pz = __uint_as_float(__shfl_sync(FULLMASK, hi, l0 + 3));
            if (cta == 0 && warp == 0 && lane == 0)
                g_fps_idx[it] = 32767 - (int)hinv;
        }
    }

    asm volatile("barrier.cluster.arrive.aligned;" ::: "memory");
    asm volatile("barrier.cluster.wait.aligned;"   ::: "memory");
}

// ---------------- KNN: warp per query, smem-chunked candidate points ----------------
#define KNN_THREADS 256
#define KNN_CHUNK   4096

__global__ void __launch_bounds__(KNN_THREADS) knn_kernel(const float* __restrict__ pos) {
    __shared__ float s_pos[KNN_CHUNK * 3];
    const int tid  = threadIdx.x;
    const int warp = tid >> 5, lane = tid & 31;
    const int m    = blockIdx.x * (KNN_THREADS / 32) + warp;

    const int qidx = g_fps_idx[m];
    const float qx = pos[qidx * 3 + 0];
    const float qy = pos[qidx * 3 + 1];
    const float qz = pos[qidx * 3 + 2];

    unsigned long long bk[KNN_K];
    #pragma unroll
    for (int i = 0; i < KNN_K; ++i) bk[i] = 0xFFFFFFFFFFFFFFFFull;
    unsigned long long worst = 0xFFFFFFFFFFFFFFFFull;
    int ws = 0;

    for (int base = 0; base < N_PTS; base += KNN_CHUNK) {
        __syncthreads();
        for (int i = tid; i < KNN_CHUNK * 3; i += KNN_THREADS)
            s_pos[i] = pos[base * 3 + i];
        __syncthreads();

        for (int j = lane; j < KNN_CHUNK; j += 32) {
            float d = dist2s(qx, qy, qz, s_pos[j * 3], s_pos[j * 3 + 1], s_pos[j * 3 + 2]);
            unsigned long long key = ((unsigned long long)__float_as_uint(d) << 32)
                                   | (unsigned int)(base + j);
            if (key < worst) {
                bk[ws] = key;
                worst = 0ull;
                #pragma unroll
                for (int i = 0; i < KNN_K; ++i)
                    if (bk[i] > worst) { worst = bk[i]; ws = i; }
            }
        }
    }

    for (int r = 0; r < KNN_K; ++r) {
        unsigned long long lm = 0xFFFFFFFFFFFFFFFFull;
        #pragma unroll
        for (int i = 0; i < KNN_K; ++i) if (bk[i] < lm) lm = bk[i];
        unsigned long long w = lm;
        #pragma unroll
        for (int off = 16; off > 0; off >>= 1) {
            unsigned long long o = __shfl_xor_sync(FULLMASK, w, off);
            if (o < w) w = o;
        }
        if (lane == 0) g_nbr[m * KNN_K + r] = (int)(w & 0xFFFFFFFFull);
        if (lm == w) {
            bool rm = false;
            #pragma unroll
            for (int i = 0; i < KNN_K; ++i)
                if (!rm && bk[i] == w) { bk[i] = 0xFFFFFFFFFFFFFFFFull; rm = true; }
        }
    }
}

// ---------------- MLP: h = relu(x @ W + b) ----------------
#define GEMM_THREADS 256
#define GEMM_ROWS    16

__global__ void __launch_bounds__(GEMM_THREADS) mlp_kernel(const float* __restrict__ x,
                                                           const float* __restrict__ W,
                                                           const float* __restrict__ b) {
    __shared__ float sW[CIN * COUT];
    __shared__ float sx[GEMM_ROWS * CIN];
    const int tid  = threadIdx.x;
    const int row0 = blockIdx.x * GEMM_ROWS;

    for (int i = tid; i < CIN * COUT; i += GEMM_THREADS) sW[i] = W[i];
    for (int i = tid; i < GEMM_ROWS * CIN; i += GEMM_THREADS) sx[i] = x[row0 * CIN + i];
    __syncthreads();

    const int c  = tid & (COUT - 1);
    const int rg = tid >> 7;
    float acc[8];
    #pragma unroll
    for (int r = 0; r < 8; ++r) acc[r] = 0.f;

    for (int k = 0; k < CIN; ++k) {
        float wv = sW[k * COUT + c];
        #pragma unroll
        for (int r = 0; r < 8; ++r)
            acc[r] = fmaf(sx[(rg * 8 + r) * CIN + k], wv, acc[r]);
    }
    float bv = b[c];
    #pragma unroll
    for (int r = 0; r < 8; ++r)
        g_h[(row0 + rg * 8 + r) * COUT + c] = fmaxf(acc[r] + bv, 0.f);
}

// ---------------- max over K neighbors ----------------
__global__ void __launch_bounds__(COUT) gather_kernel(float* __restrict__ out) {
    const int m = blockIdx.x;
    const int c = threadIdx.x;
    __shared__ int s_n[KNN_K];
    if (c < KNN_K) s_n[c] = g_nbr[m * KNN_K + c];
    __syncthreads();
    float best = g_h[s_n[0] * COUT + c];
    #pragma unroll
    for (int k = 1; k < KNN_K; ++k)
        best = fmaxf(best, g_h[s_n[k] * COUT + c]);
    out[m * COUT + c] = best;
}

// ---------------- sub_pos + sub_batch ----------------
__global__ void subpos_kernel(const float* __restrict__ pos, float* __restrict__ out) {
    const int m = blockIdx.x * blockDim.x + threadIdx.x;
    if (m < M_PTS) {
        const int idx = g_fps_idx[m];
        float* sp = out + (M_PTS * COUT);
        sp[m * 3 + 0] = pos[idx * 3 + 0];
        sp[m * 3 + 1] = pos[idx * 3 + 1];
        sp[m * 3 + 2] = pos[idx * 3 + 2];
        out[M_PTS * COUT + M_PTS * 3 + m] = 0.0f;   // sub_batch = 0
    }
}

extern "C" void kernel_launch(void* const* d_in, const int* in_sizes, int n_in,
                              void* d_out, int out_size) {
    const float* x   = (const float*)d_in[0];
    const float* pos = (const float*)d_in[1];
    const float* W   = (const float*)d_in[3];
    const float* b   = (const float*)d_in[4];
    float* out = (float*)d_out;

    zero_kernel<<<4, 1024>>>();
    hist_kernel<<<32, 1024>>>(pos);
    scan_kernel<<<1, 1024>>>();
    scatter_kernel<<<32, 1024>>>(pos);
    fps_kernel<<<FPS_CTAS, FPS_THREADS>>>(pos);
    mlp_kernel<<<N_PTS / GEMM_ROWS, GEMM_THREADS>>>(x, W, b);
    subpos_kernel<<<(M_PTS + 255) / 256, 256>>>(pos, out);
    knn_kernel<<<M_PTS / (KNN_THREADS / 32), KNN_THREADS>>>(pos);
    gather_kernel<<<M_PTS, COUT>>>(out);
}

// round 5
// speedup vs baseline: 2.4034x; 2.4034x over previous
#include <cuda_runtime.h>
#include <cstdint>

#define N_PTS 32768
#define M_PTS 8192
#define CIN   64
#define COUT  128
#define KNN_K 16

#define FPS_CTAS    4
#define FPS_THREADS 512
#define FPS_PPT     16     // 4*512*16 = 32768
#define FULLMASK    0xffffffffu

// ---------------- scratch (device globals; no allocation allowed) ----------------
__device__ int   g_fps_idx[M_PTS];
__device__ int   g_nbr[M_PTS * KNN_K];
__device__ float g_h[N_PTS * COUT];      // relu(xW+b), 16 MB
// binning scratch
__device__ int   g_cellcnt[4096];
__device__ int   g_celloff[4096];
__device__ float g_bx[N_PTS], g_by[N_PTS], g_bz[N_PTS];
__device__ int   g_bidx[N_PTS];

// strict non-FMA fp32 distance: matches XLA mul -> reduce-add (rel_err==0 verified)
__device__ __forceinline__ float dist2s(float x, float y, float z,
                                        float px, float py, float pz) {
    float dx = __fsub_rn(x, px);
    float dy = __fsub_rn(y, py);
    float dz = __fsub_rn(z, pz);
    return __fadd_rn(__fadd_rn(__fmul_rn(dx, dx), __fmul_rn(dy, dy)), __fmul_rn(dz, dz));
}

// ---------------- binning: 16^3 Morton grid ----------------
__device__ __forceinline__ int expand3(int v) {
    return (v & 1) | ((v & 2) << 2) | ((v & 4) << 4) | ((v & 8) << 6);
}
__device__ __forceinline__ int cell_of(float x, float y, float z) {
    int cx = min(15, max(0, (int)floorf((x + 4.0f) * 2.0f)));
    int cy = min(15, max(0, (int)floorf((y + 4.0f) * 2.0f)));
    int cz = min(15, max(0, (int)floorf((z + 4.0f) * 2.0f)));
    return expand3(cx) | (expand3(cy) << 1) | (expand3(cz) << 2);
}

__global__ void zero_kernel() {
    int i = blockIdx.x * blockDim.x + threadIdx.x;
    if (i < 4096) g_cellcnt[i] = 0;
}

__global__ void hist_kernel(const float* __restrict__ pos) {
    int i = blockIdx.x * blockDim.x + threadIdx.x;
    if (i < N_PTS)
        atomicAdd(&g_cellcnt[cell_of(pos[i*3], pos[i*3+1], pos[i*3+2])], 1);
}

__global__ void __launch_bounds__(1024) scan_kernel() {
    __shared__ int s_w[32];
    const int tid = threadIdx.x, lane = tid & 31, w = tid >> 5;
    int v0 = g_cellcnt[tid*4+0], v1 = g_cellcnt[tid*4+1];
    int v2 = g_cellcnt[tid*4+2], v3 = g_cellcnt[tid*4+3];
    int local = v0 + v1 + v2 + v3;
    int x = local;
    #pragma unroll
    for (int off = 1; off < 32; off <<= 1) {
        int y = __shfl_up_sync(FULLMASK, x, off);
        if (lane >= off) x += y;
    }
    if (lane == 31) s_w[w] = x;
    __syncthreads();
    if (w == 0) {
        int y = s_w[lane];
        #pragma unroll
        for (int off = 1; off < 32; off <<= 1) {
            int z = __shfl_up_sync(FULLMASK, y, off);
            if (lane >= off) y += z;
        }
        s_w[lane] = y;
    }
    __syncthreads();
    int exc = x - local + (w > 0 ? s_w[w-1] : 0);
    g_celloff[tid*4+0] = exc;
    g_celloff[tid*4+1] = exc + v0;
    g_celloff[tid*4+2] = exc + v0 + v1;
    g_celloff[tid*4+3] = exc + v0 + v1 + v2;
}

__global__ void scatter_kernel(const float* __restrict__ pos) {
    int i = blockIdx.x * blockDim.x + threadIdx.x;
    if (i < N_PTS) {
        float x = pos[i*3], y = pos[i*3+1], z = pos[i*3+2];
        int slot = atomicAdd(&g_celloff[cell_of(x, y, z)], 1);
        g_bx[slot] = x; g_by[slot] = y; g_bz[slot] = z; g_bidx[slot] = i;
    }
}

// ---------------- FPS: 4-CTA cluster, thread pruning, push exchange ----------------
// Cross-CTA words (s_in) are self-tagged, parity double-buffered:
//   key word:   val(32)<<29 | inv(15)<<14 | tag(14)   (inv = 32767-idx; max => first idx)
//   coord word: floatbits(32)<<32 | tag
// Intra-CTA hand-offs use __syncthreads (BARs park warps; R4 lesson: never all-warp spin).
__device__ __forceinline__ unsigned long long spin_word(uint32_t addr, unsigned tag) {
    unsigned long long v;
    do {
        asm volatile("ld.relaxed.cta.shared::cta.b64 %0, [%1];"
                     : "=l"(v) : "r"(addr) : "memory");
    } while ((unsigned)(v & 0x3FFFull) != tag);
    return v;
}

__global__ void __launch_bounds__(FPS_THREADS, 1) __cluster_dims__(FPS_CTAS, 1, 1)
fps_kernel(const float* __restrict__ pos) {
    __shared__ unsigned long long s_key[16];          // per-warp candidate key
    __shared__ float4 s_c[16];                        // per-warp candidate coords
    __shared__ unsigned long long s_in[2][FPS_CTAS][4]; // incoming pushes [par][src][word]
    __shared__ float s_pick[3];

    const int tid  = threadIdx.x;
    const int warp = tid >> 5, lane = tid & 31;
    const int cta  = blockIdx.x;
    const int tbase = (cta * FPS_THREADS + tid) * FPS_PPT;

    // register-resident points (Morton-binned: 16 contiguous = tight bbox)
    float X[FPS_PPT], Y[FPS_PPT], Z[FPS_PPT], Mn[FPS_PPT];
    unsigned IV2[FPS_PPT / 2];                         // packed inv indices, 15b x2
    #pragma unroll
    for (int p = 0; p < FPS_PPT; ++p) {
        X[p] = g_bx[tbase + p]; Y[p] = g_by[tbase + p]; Z[p] = g_bz[tbase + p];
        Mn[p] = __int_as_float(0x7f800000);
    }
    #pragma unroll
    for (int j = 0; j < FPS_PPT / 2; ++j)
        IV2[j] = (unsigned)(32767 - g_bidx[tbase + 2*j])
               | ((unsigned)(32767 - g_bidx[tbase + 2*j + 1]) << 15);

    // per-thread bbox (exact fmin/fmax)
    float bxmin = X[0], bxmax = X[0], bymin = Y[0], bymax = Y[0], bzmin = Z[0], bzmax = Z[0];
    #pragma unroll
    for (int p = 1; p < FPS_PPT; ++p) {
        bxmin = fminf(bxmin, X[p]); bxmax = fmaxf(bxmax, X[p]);
        bymin = fminf(bymin, Y[p]); bymax = fmaxf(bymax, Y[p]);
        bzmin = fminf(bzmin, Z[p]); bzmax = fmaxf(bzmax, Z[p]);
    }

    // per-thread cached candidate
    float bv = __int_as_float(0x7f800000);   // max of Mn (prune threshold); round1 updates all
    unsigned bi = 0;
    float bcx = 0.f, bcy = 0.f, bcz = 0.f;

    // zero tagged slots (tag 0 never matches it>=1)
    if (tid < 2 * FPS_CTAS * 4) ((unsigned long long*)s_in)[tid] = 0ull;
    __syncthreads();

    const uint32_t in_l = (uint32_t)__cvta_generic_to_shared(&s_in[0][0][0]);
    uint32_t push_addr = 0;
    if (warp == 0) {
        const int idx = lane & 15;               // src*4+word pattern, duplicated 16..31
        uint32_t pa;
        asm("mapa.shared::cluster.u32 %0, %1, %2;"
            : "=r"(pa) : "r"(in_l), "r"(idx >> 2));       // peer = idx>>2
        push_addr = pa + (uint32_t)((cta * 4 + (idx & 3)) * 8);  // my slot, word idx&3
    }

    float px = pos[0], py = pos[1], pz = pos[2];
    if (cta == 0 && tid == 0) g_fps_idx[0] = 0;

    // all CTAs' s_in zeroed before any push can arrive
    asm volatile("barrier.cluster.arrive.aligned;" ::: "memory");
    asm volatile("barrier.cluster.wait.aligned;"   ::: "memory");

    for (int it = 1; it < M_PTS; ++it) {
        const unsigned tag = (unsigned)it;       // < 16384
        const int par = it & 1;

        // ---- stage A: per-thread prune / update / rescan ----
        float dxl = fmaxf(0.f, fmaxf(__fsub_rn(bxmin, px), __fsub_rn(px, bxmax)));
        float dyl = fmaxf(0.f, fmaxf(__fsub_rn(bymin, py), __fsub_rn(py, bymax)));
        float dzl = fmaxf(0.f, fmaxf(__fsub_rn(bzmin, pz), __fsub_rn(pz, bzmax)));
        float dlb = __fadd_rn(__fadd_rn(__fmul_rn(dxl, dxl), __fmul_rn(dyl, dyl)),
                              __fmul_rn(dzl, dzl));

        if (dlb < bv) {        // else: fminf provably no-op for all 16 pts -> cache valid
            float nv = -1.f; unsigned ni = 0;
            float ncx = 0.f, ncy = 0.f, ncz = 0.f;
            #pragma unroll
            for (int p = 0; p < FPS_PPT; ++p) {
                float d = dist2s(X[p], Y[p], Z[p], px, py, pz);
                Mn[p] = fminf(Mn[p], d);
                unsigned iv = (p & 1) ? ((IV2[p >> 1] >> 15) & 0x7fffu)
                                      : (IV2[p >> 1] & 0x7fffu);
                if (Mn[p] > nv || (Mn[p] == nv && iv > ni)) {
                    nv = Mn[p]; ni = iv; ncx = X[p]; ncy = Y[p]; ncz = Z[p];
                }
            }
            bv = nv; bi = ni; bcx = ncx; bcy = ncy; bcz = ncz;
        }

        // warp candidate: REDUX (max val, then max inv among matches => first orig idx)
        unsigned uv   = __float_as_uint(bv);     // bv >= 0 finite after round1
        unsigned wmax = __reduce_max_sync(FULLMASK, uv);
        unsigned winv = __reduce_max_sync(FULLMASK, (uv == wmax) ? bi : 0u);
        int wl = __ffs(__ballot_sync(FULLMASK, uv == wmax && bi == winv)) - 1;
        if (lane == wl) {
            s_key[warp] = ((unsigned long long)wmax << 29)
                        | ((unsigned long long)winv << 14);
            s_c[warp] = make_float4(bcx, bcy, bcz, 0.f);
        }
        __syncthreads();   // BAR1: s_key/s_c published

        // ---- warp0: CTA reduce -> push to all 4 CTAs -> spin local -> cluster reduce ----
        if (warp == 0) {
            unsigned long long k = (lane < 16) ? s_key[lane] : 0ull;
            unsigned val = (unsigned)(k >> 29);
            unsigned inv = (unsigned)((k >> 14) & 0x7fffull);
            unsigned cmax = __reduce_max_sync(FULLMASK, val);
            unsigned cinv = __reduce_max_sync(FULLMASK, (val == cmax) ? inv : 0u);
            int cl = __ffs(__ballot_sync(FULLMASK,
                         lane < 16 && val == cmax && inv == cinv)) - 1;
            float4 cc = s_c[cl];                 // broadcast LDS.128

            const int idx = lane & 15, word = idx & 3;
            unsigned long long pw;
            if (word == 0)
                pw = ((unsigned long long)cmax << 29)
                   | ((unsigned long long)cinv << 14) | tag;
            else {
                float c = (word == 1) ? cc.x : (word == 2) ? cc.y : cc.z;
                pw = ((unsigned long long)__float_as_uint(c) << 32) | tag;
            }
            if (lane < 16)
                asm volatile("st.relaxed.cluster.shared::cluster.b64 [%0], %1;"
                             :: "r"(push_addr + (uint32_t)(par * 128)), "l"(pw) : "memory");

            // spin on LOCAL incoming words (remote stores need no local issue)
            unsigned long long g = spin_word(
                in_l + (uint32_t)(par * 128 + idx * 8), tag);

            const bool iskey = (word == 0);
            unsigned v2 = iskey ? (unsigned)(g >> 29) : 0u;
            unsigned m2 = __reduce_max_sync(FULLMASK, v2);
            unsigned gi = (unsigned)((g >> 14) & 0x7fffull);
            unsigned i2 = __reduce_max_sync(FULLMASK, (iskey && v2 == m2) ? gi : 0u);
            int l0 = __ffs(__ballot_sync(FULLMASK,
                         iskey && v2 == m2 && gi == i2)) - 1;
            unsigned hi = (unsigned)(g >> 32);
            float fx = __uint_as_float(__shfl_sync(FULLMASK, hi, l0 + 1));
            float fy = __uint_as_float(__shfl_sync(FULLMASK, hi, l0 + 2));
            float fz = __uint_as_float(__shfl_sync(FULLMASK, hi, l0 + 3));
            if (lane == 0) {
                s_pick[0] = fx; s_pick[1] = fy; s_pick[2] = fz;
                if (cta == 0) g_fps_idx[it] = 32767 - (int)i2;
            }
        }
        __syncthreads();   // BAR2: s_pick published
        px = s_pick[0]; py = s_pick[1]; pz = s_pick[2];
    }

    // no CTA may exit while peers might still push to its s_in
    asm volatile("barrier.cluster.arrive.aligned;" ::: "memory");
    asm volatile("barrier.cluster.wait.aligned;"   ::: "memory");
}

// ---------------- KNN: warp per query, smem-chunked candidate points ----------------
#define KNN_THREADS 256
#define KNN_CHUNK   4096

__global__ void __launch_bounds__(KNN_THREADS) knn_kernel(const float* __restrict__ pos) {
    __shared__ float s_pos[KNN_CHUNK * 3];
    const int tid  = threadIdx.x;
    const int warp = tid >> 5, lane = tid & 31;
    const int m    = blockIdx.x * (KNN_THREADS / 32) + warp;

    const int qidx = g_fps_idx[m];
    const float qx = pos[qidx * 3 + 0];
    const float qy = pos[qidx * 3 + 1];
    const float qz = pos[qidx * 3 + 2];

    unsigned long long bk[KNN_K];
    #pragma unroll
    for (int i = 0; i < KNN_K; ++i) bk[i] = 0xFFFFFFFFFFFFFFFFull;
    unsigned long long worst = 0xFFFFFFFFFFFFFFFFull;
    int ws = 0;

    for (int base = 0; base < N_PTS; base += KNN_CHUNK) {
        __syncthreads();
        for (int i = tid; i < KNN_CHUNK * 3; i += KNN_THREADS)
            s_pos[i] = pos[base * 3 + i];
        __syncthreads();

        for (int j = lane; j < KNN_CHUNK; j += 32) {
            float d = dist2s(qx, qy, qz, s_pos[j * 3], s_pos[j * 3 + 1], s_pos[j * 3 + 2]);
            unsigned long long key = ((unsigned long long)__float_as_uint(d) << 32)
                                   | (unsigned int)(base + j);
            if (key < worst) {
                bk[ws] = key;
                worst = 0ull;
                #pragma unroll
                for (int i = 0; i < KNN_K; ++i)
                    if (bk[i] > worst) { worst = bk[i]; ws = i; }
            }
        }
    }

    for (int r = 0; r < KNN_K; ++r) {
        unsigned long long lm = 0xFFFFFFFFFFFFFFFFull;
        #pragma unroll
        for (int i = 0; i < KNN_K; ++i) if (bk[i] < lm) lm = bk[i];
        unsigned long long w = lm;
        #pragma unroll
        for (int off = 16; off > 0; off >>= 1) {
            unsigned long long o = __shfl_xor_sync(FULLMASK, w, off);
            if (o < w) w = o;
        }
        if (lane == 0) g_nbr[m * KNN_K + r] = (int)(w & 0xFFFFFFFFull);
        if (lm == w) {
            bool rm = false;
            #pragma unroll
            for (int i = 0; i < KNN_K; ++i)
                if (!rm && bk[i] == w) { bk[i] = 0xFFFFFFFFFFFFFFFFull; rm = true; }
        }
    }
}

// ---------------- MLP: h = relu(x @ W + b) ----------------
#define GEMM_THREADS 256
#define GEMM_ROWS    16

__global__ void __launch_bounds__(GEMM_THREADS) mlp_kernel(const float* __restrict__ x,
                                                           const float* __restrict__ W,
                                                           const float* __restrict__ b) {
    __shared__ float sW[CIN * COUT];
    __shared__ float sx[GEMM_ROWS * CIN];
    const int tid  = threadIdx.x;
    const int row0 = blockIdx.x * GEMM_ROWS;

    for (int i = tid; i < CIN * COUT; i += GEMM_THREADS) sW[i] = W[i];
    for (int i = tid; i < GEMM_ROWS * CIN; i += GEMM_THREADS) sx[i] = x[row0 * CIN + i];
    __syncthreads();

    const int c  = tid & (COUT - 1);
    const int rg = tid >> 7;
    float acc[8];
    #pragma unroll
    for (int r = 0; r < 8; ++r) acc[r] = 0.f;

    for (int k = 0; k < CIN; ++k) {
        float wv = sW[k * COUT + c];
        #pragma unroll
        for (int r = 0; r < 8; ++r)
            acc[r] = fmaf(sx[(rg * 8 + r) * CIN + k], wv, acc[r]);
    }
    float bv = b[c];
    #pragma unroll
    for (int r = 0; r < 8; ++r)
        g_h[(row0 + rg * 8 + r) * COUT + c] = fmaxf(acc[r] + bv, 0.f);
}

// ---------------- max over K neighbors ----------------
__global__ void __launch_bounds__(COUT) gather_kernel(float* __restrict__ out) {
    const int m = blockIdx.x;
    const int c = threadIdx.x;
    __shared__ int s_n[KNN_K];
    if (c < KNN_K) s_n[c] = g_nbr[m * KNN_K + c];
    __syncthreads();
    float best = g_h[s_n[0] * COUT + c];
    #pragma unroll
    for (int k = 1; k < KNN_K; ++k)
        best = fmaxf(best, g_h[s_n[k] * COUT + c]);
    out[m * COUT + c] = best;
}

// ---------------- sub_pos + sub_batch ----------------
__global__ void subpos_kernel(const float* __restrict__ pos, float* __restrict__ out) {
    const int m = blockIdx.x * blockDim.x + threadIdx.x;
    if (m < M_PTS) {
        const int idx = g_fps_idx[m];
        float* sp = out + (M_PTS * COUT);
        sp[m * 3 + 0] = pos[idx * 3 + 0];
        sp[m * 3 + 1] = pos[idx * 3 + 1];
        sp[m * 3 + 2] = pos[idx * 3 + 2];
        out[M_PTS * COUT + M_PTS * 3 + m] = 0.0f;   // sub_batch = 0
    }
}

extern "C" void kernel_launch(void* const* d_in, const int* in_sizes, int n_in,
                              void* d_out, int out_size) {
    const float* x   = (const float*)d_in[0];
    const float* pos = (const float*)d_in[1];
    const float* W   = (const float*)d_in[3];
    const float* b   = (const float*)d_in[4];
    float* out = (float*)d_out;

    zero_kernel<<<4, 1024>>>();
    hist_kernel<<<32, 1024>>>(pos);
    scan_kernel<<<1, 1024>>>();
    scatter_kernel<<<32, 1024>>>(pos);
    fps_kernel<<<FPS_CTAS, FPS_THREADS>>>(pos);
    mlp_kernel<<<N_PTS / GEMM_ROWS, GEMM_THREADS>>>(x, W, b);
    subpos_kernel<<<(M_PTS + 255) / 256, 256>>>(pos, out);
    knn_kernel<<<M_PTS / (KNN_THREADS / 32), KNN_THREADS>>>(pos);
    gather_kernel<<<M_PTS, COUT>>>(out);
}

// round 6
// speedup vs baseline: 3.5796x; 1.4894x over previous
#include <cuda_runtime.h>
#include <cstdint>

#define N_PTS 32768
#define M_PTS 8192
#define CIN   64
#define COUT  128
#define KNN_K 16

#define FPS_CTAS    8
#define FPS_THREADS 1024
#define FPS_PPT     4      // 8*1024*4 = 32768
#define FULLMASK    0xffffffffu

// ---------------- scratch (device globals; no allocation allowed) ----------------
__device__ int   g_fps_idx[M_PTS];
__device__ int   g_nbr[M_PTS * KNN_K];
__device__ float g_h[N_PTS * COUT];      // relu(xW+b), 16 MB
// binning scratch
__device__ int   g_cellcnt[4096];
__device__ int   g_celloff[4096];
__device__ float g_bx[N_PTS], g_by[N_PTS], g_bz[N_PTS];
__device__ int   g_bidx[N_PTS];

// strict non-FMA fp32 distance: matches XLA mul -> reduce-add (rel_err==0 verified)
__device__ __forceinline__ float dist2s(float x, float y, float z,
                                        float px, float py, float pz) {
    float dx = __fsub_rn(x, px);
    float dy = __fsub_rn(y, py);
    float dz = __fsub_rn(z, pz);
    return __fadd_rn(__fadd_rn(__fmul_rn(dx, dx), __fmul_rn(dy, dy)), __fmul_rn(dz, dz));
}

// ---------------- binning: 16^3 Morton grid ----------------
__device__ __forceinline__ int expand3(int v) {
    return (v & 1) | ((v & 2) << 2) | ((v & 4) << 4) | ((v & 8) << 6);
}
__device__ __forceinline__ int cell_of(float x, float y, float z) {
    int cx = min(15, max(0, (int)floorf((x + 4.0f) * 2.0f)));
    int cy = min(15, max(0, (int)floorf((y + 4.0f) * 2.0f)));
    int cz = min(15, max(0, (int)floorf((z + 4.0f) * 2.0f)));
    return expand3(cx) | (expand3(cy) << 1) | (expand3(cz) << 2);
}

__global__ void zero_kernel() {
    int i = blockIdx.x * blockDim.x + threadIdx.x;
    if (i < 4096) g_cellcnt[i] = 0;
}

__global__ void hist_kernel(const float* __restrict__ pos) {
    int i = blockIdx.x * blockDim.x + threadIdx.x;
    if (i < N_PTS)
        atomicAdd(&g_cellcnt[cell_of(pos[i*3], pos[i*3+1], pos[i*3+2])], 1);
}

__global__ void __launch_bounds__(1024) scan_kernel() {
    __shared__ int s_w[32];
    const int tid = threadIdx.x, lane = tid & 31, w = tid >> 5;
    int v0 = g_cellcnt[tid*4+0], v1 = g_cellcnt[tid*4+1];
    int v2 = g_cellcnt[tid*4+2], v3 = g_cellcnt[tid*4+3];
    int local = v0 + v1 + v2 + v3;
    int x = local;
    #pragma unroll
    for (int off = 1; off < 32; off <<= 1) {
        int y = __shfl_up_sync(FULLMASK, x, off);
        if (lane >= off) x += y;
    }
    if (lane == 31) s_w[w] = x;
    __syncthreads();
    if (w == 0) {
        int y = s_w[lane];
        #pragma unroll
        for (int off = 1; off < 32; off <<= 1) {
            int z = __shfl_up_sync(FULLMASK, y, off);
            if (lane >= off) y += z;
        }
        s_w[lane] = y;
    }
    __syncthreads();
    int exc = x - local + (w > 0 ? s_w[w-1] : 0);
    g_celloff[tid*4+0] = exc;
    g_celloff[tid*4+1] = exc + v0;
    g_celloff[tid*4+2] = exc + v0 + v1;
    g_celloff[tid*4+3] = exc + v0 + v1 + v2;
}

__global__ void scatter_kernel(const float* __restrict__ pos) {
    int i = blockIdx.x * blockDim.x + threadIdx.x;
    if (i < N_PTS) {
        float x = pos[i*3], y = pos[i*3+1], z = pos[i*3+2];
        int slot = atomicAdd(&g_celloff[cell_of(x, y, z)], 1);
        g_bx[slot] = x; g_by[slot] = y; g_bz[slot] = z; g_bidx[slot] = i;
    }
}

// ---------------- FPS: R3 structure + push-based exchange ----------------
// push word layout (self-tagged, parity double-buffered):
//   key word:   val(32)<<32 | inv(15)<<17 | tag(14)  (inv = 32767-idx; max => first idx)
//   coord word: floatbits(32)<<32 | tag
__device__ __forceinline__ unsigned long long spin_local(uint32_t addr, unsigned tag) {
    unsigned long long v;
    do {
        asm volatile("ld.relaxed.cta.shared::cta.b64 %0, [%1];"
                     : "=l"(v) : "r"(addr) : "memory");
    } while ((unsigned)(v & 0x3FFFull) != tag);
    return v;
}

__global__ void __launch_bounds__(FPS_THREADS, 1) __cluster_dims__(FPS_CTAS, 1, 1)
fps_kernel(const float* __restrict__ pos) {
    __shared__ unsigned long long s_in[2][FPS_CTAS][4];  // incoming pushes [par][src][word]
    __shared__ unsigned s_val[32], s_idx[32];
    __shared__ float s_wx[32], s_wy[32], s_wz[32];
    __shared__ float s_pick[3];

    const int tid  = threadIdx.x;
    const int warp = tid >> 5, lane = tid & 31;
    const int cta  = blockIdx.x;
    const int wbase = (cta * 32 + warp) * 128;      // this warp's 128 binned points

    float X[FPS_PPT], Y[FPS_PPT], Z[FPS_PPT], Mn[FPS_PPT];
    unsigned I[FPS_PPT];
    #pragma unroll
    for (int p = 0; p < FPS_PPT; ++p) {
        int j = wbase + lane + p * 32;
        X[p] = g_bx[j]; Y[p] = g_by[j]; Z[p] = g_bz[j];
        I[p] = (unsigned)g_bidx[j];
        Mn[p] = __int_as_float(0x7f800000);
    }

    // warp bbox (one-time)
    float bxmin = fminf(fminf(X[0], X[1]), fminf(X[2], X[3]));
    float bxmax = fmaxf(fmaxf(X[0], X[1]), fmaxf(X[2], X[3]));
    float bymin = fminf(fminf(Y[0], Y[1]), fminf(Y[2], Y[3]));
    float bymax = fmaxf(fmaxf(Y[0], Y[1]), fmaxf(Y[2], Y[3]));
    float bzmin = fminf(fminf(Z[0], Z[1]), fminf(Z[2], Z[3]));
    float bzmax = fmaxf(fmaxf(Z[0], Z[1]), fmaxf(Z[2], Z[3]));
    #pragma unroll
    for (int off = 16; off > 0; off >>= 1) {
        bxmin = fminf(bxmin, __shfl_xor_sync(FULLMASK, bxmin, off));
        bxmax = fmaxf(bxmax, __shfl_xor_sync(FULLMASK, bxmax, off));
        bymin = fminf(bymin, __shfl_xor_sync(FULLMASK, bymin, off));
        bymax = fmaxf(bymax, __shfl_xor_sync(FULLMASK, bymax, off));
        bzmin = fminf(bzmin, __shfl_xor_sync(FULLMASK, bzmin, off));
        bzmax = fmaxf(bzmax, __shfl_xor_sync(FULLMASK, bzmax, off));
    }

    float wval = __int_as_float(0x7f800000);   // warp skip threshold (cached max-mind)

    // zero tagged slots (tag 0 never matches it>=1)
    if (tid < 2 * FPS_CTAS * 4) ((unsigned long long*)s_in)[tid] = 0ull;

    const uint32_t in_l = (uint32_t)__cvta_generic_to_shared(&s_in[0][0][0]);
    // warp0 push address: lane -> peer (lane>>2), my slot (cta), word (lane&3)
    uint32_t push_addr = 0;
    if (warp == 0) {
        uint32_t pa;
        asm("mapa.shared::cluster.u32 %0, %1, %2;"
            : "=r"(pa) : "r"(in_l), "r"(lane >> 2));
        push_addr = pa + (uint32_t)((cta * 4 + (lane & 3)) * 8);
    }

    float px = pos[0], py = pos[1], pz = pos[2];   // first pick = index 0
    if (cta == 0 && tid == 0) g_fps_idx[0] = 0;

    // all CTAs' s_in zeroed before any push can arrive
    asm volatile("barrier.cluster.arrive.aligned;" ::: "memory");
    asm volatile("barrier.cluster.wait.aligned;"   ::: "memory");

    for (int it = 1; it < M_PTS; ++it) {
        // exact-safe lower bound: rn rounding is monotone, so d_lb <= every lane's fp dist
        float dxl = fmaxf(0.f, fmaxf(__fsub_rn(bxmin, px), __fsub_rn(px, bxmax)));
        float dyl = fmaxf(0.f, fmaxf(__fsub_rn(bymin, py), __fsub_rn(py, bymax)));
        float dzl = fmaxf(0.f, fmaxf(__fsub_rn(bzmin, pz), __fsub_rn(pz, bzmax)));
        float dlb = __fadd_rn(__fadd_rn(__fmul_rn(dxl, dxl), __fmul_rn(dyl, dyl)),
                              __fmul_rn(dzl, dzl));

        if (dlb < wval) {                      // warp-uniform branch
            #pragma unroll
            for (int p = 0; p < FPS_PPT; ++p)
                Mn[p] = fminf(Mn[p], dist2s(X[p], Y[p], Z[p], px, py, pz));

            // thread-local argmax, min-orig-idx tie-break
            float bv = Mn[0]; unsigned bi = I[0];
            float bx = X[0], by = Y[0], bz = Z[0];
            #pragma unroll
            for (int p = 1; p < FPS_PPT; ++p) {
                if (Mn[p] > bv || (Mn[p] == bv && I[p] < bi)) {
                    bv = Mn[p]; bi = I[p]; bx = X[p]; by = Y[p]; bz = Z[p];
                }
            }
            unsigned vb   = __float_as_uint(bv);
            unsigned wmax = __reduce_max_sync(FULLMASK, vb);
            unsigned widx = __reduce_min_sync(FULLMASK, (vb == wmax) ? bi : 0xffffffffu);
            wval = __uint_as_float(wmax);
            if (vb == wmax && bi == widx) {    // unique winner lane stores candidate
                s_val[warp] = wmax; s_idx[warp] = widx;
                s_wx[warp] = bx; s_wy[warp] = by; s_wz[warp] = bz;
            }
        }
        // else: cached smem candidate from last update round is still exact
        __syncthreads();   // BAR1: warp candidates published

        if (warp == 0) {
            // CTA reduce over 32 warp winners
            unsigned v  = s_val[lane], ix = s_idx[lane];
            float xw = s_wx[lane], yw = s_wy[lane], zw = s_wz[lane];
            unsigned cmax = __reduce_max_sync(FULLMASK, v);
            unsigned cidx = __reduce_min_sync(FULLMASK, (v == cmax) ? ix : 0xffffffffu);
            int wl = __ffs(__ballot_sync(FULLMASK, v == cmax && ix == cidx)) - 1;
            float cx = __shfl_sync(FULLMASK, xw, wl);
            float cy = __shfl_sync(FULLMASK, yw, wl);
            float cz = __shfl_sync(FULLMASK, zw, wl);

            const unsigned tag = (unsigned)it;          // < 16384
            const int par = it & 1;

            // push my CTA candidate to ALL 8 CTAs (one word per lane; 8x4 = 32)
            const int word = lane & 3;
            unsigned long long pw;
            if (word == 0)
                pw = ((unsigned long long)cmax << 32)
                   | ((unsigned long long)(32767u - cidx) << 17)
                   | (unsigned long long)tag;
            else {
                float c = (word == 1) ? cx : (word == 2) ? cy : cz;
                pw = ((unsigned long long)__float_as_uint(c) << 32) | tag;
            }
            asm volatile("st.relaxed.cluster.shared::cluster.b64 [%0], %1;"
                         :: "r"(push_addr + (uint32_t)(par * 256)), "l"(pw) : "memory");

            // spin on LOCAL incoming words (remote stores land without local issue)
            unsigned long long g = spin_local(
                in_l + (uint32_t)(par * 256 + lane * 8), tag);

            const bool iskey = (word == 0);
            unsigned hval = iskey ? (unsigned)(g >> 32) : 0u;
            unsigned hmax = __reduce_max_sync(FULLMASK, hval);
            unsigned ginv = (unsigned)((g >> 17) & 0x7FFFull);
            unsigned hinv = __reduce_max_sync(FULLMASK,
                                (iskey && hval == hmax) ? ginv : 0u);
            int l0 = __ffs(__ballot_sync(FULLMASK,
                        iskey && hval == hmax && ginv == hinv)) - 1;
            unsigned hi = (unsigned)(g >> 32);
            float pkx = __uint_as_float(__shfl_sync(FULLMASK, hi, l0 + 1));
            float pky = __uint_as_float(__shfl_sync(FULLMASK, hi, l0 + 2));
            float pkz = __uint_as_float(__shfl_sync(FULLMASK, hi, l0 + 3));
            if (lane == 0) {
                s_pick[0] = pkx; s_pick[1] = pky; s_pick[2] = pkz;
                if (cta == 0) g_fps_idx[it] = 32767 - (int)hinv;
            }
        }
        __syncthreads();   // BAR2: s_pick published
        px = s_pick[0]; py = s_pick[1]; pz = s_pick[2];
    }

    // no CTA may exit while peers might still push to its s_in
    asm volatile("barrier.cluster.arrive.aligned;" ::: "memory");
    asm volatile("barrier.cluster.wait.aligned;"   ::: "memory");
}

// ---------------- KNN: warp per query, smem-chunked candidate points ----------------
#define KNN_THREADS 256
#define KNN_CHUNK   4096

__global__ void __launch_bounds__(KNN_THREADS) knn_kernel(const float* __restrict__ pos) {
    __shared__ float s_pos[KNN_CHUNK * 3];
    const int tid  = threadIdx.x;
    const int warp = tid >> 5, lane = tid & 31;
    const int m    = blockIdx.x * (KNN_THREADS / 32) + warp;

    const int qidx = g_fps_idx[m];
    const float qx = pos[qidx * 3 + 0];
    const float qy = pos[qidx * 3 + 1];
    const float qz = pos[qidx * 3 + 2];

    unsigned long long bk[KNN_K];
    #pragma unroll
    for (int i = 0; i < KNN_K; ++i) bk[i] = 0xFFFFFFFFFFFFFFFFull;
    unsigned long long worst = 0xFFFFFFFFFFFFFFFFull;
    int ws = 0;

    for (int base = 0; base < N_PTS; base += KNN_CHUNK) {
        __syncthreads();
        for (int i = tid; i < KNN_CHUNK * 3; i += KNN_THREADS)
            s_pos[i] = pos[base * 3 + i];
        __syncthreads();

        for (int j = lane; j < KNN_CHUNK; j += 32) {
            float d = dist2s(qx, qy, qz, s_pos[j * 3], s_pos[j * 3 + 1], s_pos[j * 3 + 2]);
            unsigned long long key = ((unsigned long long)__float_as_uint(d) << 32)
                                   | (unsigned int)(base + j);
            if (key < worst) {
                bk[ws] = key;
                worst = 0ull;
                #pragma unroll
                for (int i = 0; i < KNN_K; ++i)
                    if (bk[i] > worst) { worst = bk[i]; ws = i; }
            }
        }
    }

    for (int r = 0; r < KNN_K; ++r) {
        unsigned long long lm = 0xFFFFFFFFFFFFFFFFull;
        #pragma unroll
        for (int i = 0; i < KNN_K; ++i) if (bk[i] < lm) lm = bk[i];
        unsigned long long w = lm;
        #pragma unroll
        for (int off = 16; off > 0; off >>= 1) {
            unsigned long long o = __shfl_xor_sync(FULLMASK, w, off);
            if (o < w) w = o;
        }
        if (lane == 0) g_nbr[m * KNN_K + r] = (int)(w & 0xFFFFFFFFull);
        if (lm == w) {
            bool rm = false;
            #pragma unroll
            for (int i = 0; i < KNN_K; ++i)
                if (!rm && bk[i] == w) { bk[i] = 0xFFFFFFFFFFFFFFFFull; rm = true; }
        }
    }
}

// ---------------- MLP: h = relu(x @ W + b) ----------------
#define GEMM_THREADS 256
#define GEMM_ROWS    16

__global__ void __launch_bounds__(GEMM_THREADS) mlp_kernel(const float* __restrict__ x,
                                                           const float* __restrict__ W,
                                                           const float* __restrict__ b) {
    __shared__ float sW[CIN * COUT];
    __shared__ float sx[GEMM_ROWS * CIN];
    const int tid  = threadIdx.x;
    const int row0 = blockIdx.x * GEMM_ROWS;

    for (int i = tid; i < CIN * COUT; i += GEMM_THREADS) sW[i] = W[i];
    for (int i = tid; i < GEMM_ROWS * CIN; i += GEMM_THREADS) sx[i] = x[row0 * CIN + i];
    __syncthreads();

    const int c  = tid & (COUT - 1);
    const int rg = tid >> 7;
    float acc[8];
    #pragma unroll
    for (int r = 0; r < 8; ++r) acc[r] = 0.f;

    for (int k = 0; k < CIN; ++k) {
        float wv = sW[k * COUT + c];
        #pragma unroll
        for (int r = 0; r < 8; ++r)
            acc[r] = fmaf(sx[(rg * 8 + r) * CIN + k], wv, acc[r]);
    }
    float bv = b[c];
    #pragma unroll
    for (int r = 0; r < 8; ++r)
        g_h[(row0 + rg * 8 + r) * COUT + c] = fmaxf(acc[r] + bv, 0.f);
}

// ---------------- max over K neighbors ----------------
__global__ void __launch_bounds__(COUT) gather_kernel(float* __restrict__ out) {
    const int m = blockIdx.x;
    const int c = threadIdx.x;
    __shared__ int s_n[KNN_K];
    if (c < KNN_K) s_n[c] = g_nbr[m * KNN_K + c];
    __syncthreads();
    float best = g_h[s_n[0] * COUT + c];
    #pragma unroll
    for (int k = 1; k < KNN_K; ++k)
        best = fmaxf(best, g_h[s_n[k] * COUT + c]);
    out[m * COUT + c] = best;
}

// ---------------- sub_pos + sub_batch ----------------
__global__ void subpos_kernel(const float* __restrict__ pos, float* __restrict__ out) {
    const int m = blockIdx.x * blockDim.x + threadIdx.x;
    if (m < M_PTS) {
        const int idx = g_fps_idx[m];
        float* sp = out + (M_PTS * COUT);
        sp[m * 3 + 0] = pos[idx * 3 + 0];
        sp[m * 3 + 1] = pos[idx * 3 + 1];
        sp[m * 3 + 2] = pos[idx * 3 + 2];
        out[M_PTS * COUT + M_PTS * 3 + m] = 0.0f;   // sub_batch = 0
    }
}

extern "C" void kernel_launch(void* const* d_in, const int* in_sizes, int n_in,
                              void* d_out, int out_size) {
    const float* x   = (const float*)d_in[0];
    const float* pos = (const float*)d_in[1];
    const float* W   = (const float*)d_in[3];
    const float* b   = (const float*)d_in[4];
    float* out = (float*)d_out;

    zero_kernel<<<4, 1024>>>();
    hist_kernel<<<32, 1024>>>(pos);
    scan_kernel<<<1, 1024>>>();
    scatter_kernel<<<32, 1024>>>(pos);
    fps_kernel<<<FPS_CTAS, FPS_THREADS>>>(pos);
    mlp_kernel<<<N_PTS / GEMM_ROWS, GEMM_THREADS>>>(x, W, b);
    subpos_kernel<<<(M_PTS + 255) / 256, 256>>>(pos, out);
    knn_kernel<<<M_PTS / (KNN_THREADS / 32), KNN_THREADS>>>(pos);
    gather_kernel<<<M_PTS, COUT>>>(out);
}

// round 9
// speedup vs baseline: 4.2776x; 1.1950x over previous
#include <cuda_runtime.h>
#include <cstdint>

#define N_PTS 32768
#define M_PTS 8192
#define CIN   64
#define COUT  128
#define KNN_K 16

#define FPS_CTAS    8
#define FPS_THREADS 512
#define FPS_PPT     8      // 8*512*8 = 32768
#define FPS_WARPS   (FPS_THREADS / 32)
#define FULLMASK    0xffffffffu

// ---------------- scratch (device globals; no allocation allowed) ----------------
__device__ int   g_fps_idx[M_PTS];
__device__ int   g_nbr[M_PTS * KNN_K];
__device__ float g_h[N_PTS * COUT];      // relu(xW+b), 16 MB
// binning scratch
__device__ int   g_cellcnt[4096];        // zero-init; scan re-zeroes after reading
__device__ int   g_celloff[4096];
__device__ float g_bx[N_PTS], g_by[N_PTS], g_bz[N_PTS];
__device__ int   g_bidx[N_PTS];

// strict non-FMA fp32 distance: matches XLA mul -> reduce-add (rel_err==0 verified)
__device__ __forceinline__ float dist2s(float x, float y, float z,
                                        float px, float py, float pz) {
    float dx = __fsub_rn(x, px);
    float dy = __fsub_rn(y, py);
    float dz = __fsub_rn(z, pz);
    return __fadd_rn(__fadd_rn(__fmul_rn(dx, dx), __fmul_rn(dy, dy)), __fmul_rn(dz, dz));
}

// ---------------- binning: 16^3 Morton grid ----------------
__device__ __forceinline__ int expand3(int v) {
    return (v & 1) | ((v & 2) << 2) | ((v & 4) << 4) | ((v & 8) << 6);
}
__device__ __forceinline__ int cell_of(float x, float y, float z) {
    int cx = min(15, max(0, (int)floorf((x + 4.0f) * 2.0f)));
    int cy = min(15, max(0, (int)floorf((y + 4.0f) * 2.0f)));
    int cz = min(15, max(0, (int)floorf((z + 4.0f) * 2.0f)));
    return expand3(cx) | (expand3(cy) << 1) | (expand3(cz) << 2);
}

__global__ void hist_kernel(const float* __restrict__ pos) {
    int i = blockIdx.x * blockDim.x + threadIdx.x;
    if (i < N_PTS)
        atomicAdd(&g_cellcnt[cell_of(pos[i*3], pos[i*3+1], pos[i*3+2])], 1);
}

// scan ALSO re-zeroes g_cellcnt after reading it, so each graph replay is clean
__global__ void __launch_bounds__(1024) scan_kernel() {
    __shared__ int s_w[32];
    const int tid = threadIdx.x, lane = tid & 31, w = tid >> 5;
    int v0 = g_cellcnt[tid*4+0], v1 = g_cellcnt[tid*4+1];
    int v2 = g_cellcnt[tid*4+2], v3 = g_cellcnt[tid*4+3];
    g_cellcnt[tid*4+0] = 0; g_cellcnt[tid*4+1] = 0;
    g_cellcnt[tid*4+2] = 0; g_cellcnt[tid*4+3] = 0;
    int local = v0 + v1 + v2 + v3;
    int x = local;
    #pragma unroll
    for (int off = 1; off < 32; off <<= 1) {
        int y = __shfl_up_sync(FULLMASK, x, off);
        if (lane >= off) x += y;
    }
    if (lane == 31) s_w[w] = x;
    __syncthreads();
    if (w == 0) {
        int y = s_w[lane];
        #pragma unroll
        for (int off = 1; off < 32; off <<= 1) {
            int z = __shfl_up_sync(FULLMASK, y, off);
            if (lane >= off) y += z;
        }
        s_w[lane] = y;
    }
    __syncthreads();
    int exc = x - local + (w > 0 ? s_w[w-1] : 0);
    g_celloff[tid*4+0] = exc;
    g_celloff[tid*4+1] = exc + v0;
    g_celloff[tid*4+2] = exc + v0 + v1;
    g_celloff[tid*4+3] = exc + v0 + v1 + v2;
}

__global__ void scatter_kernel(const float* __restrict__ pos) {
    int i = blockIdx.x * blockDim.x + threadIdx.x;
    if (i < N_PTS) {
        float x = pos[i*3], y = pos[i*3+1], z = pos[i*3+2];
        int slot = atomicAdd(&g_celloff[cell_of(x, y, z)], 1);
        g_bx[slot] = x; g_by[slot] = y; g_bz[slot] = z; g_bidx[slot] = i;
    }
}

// ---------------- FPS: 8-CTA cluster, 16 warps, pull exchange (R3 structure) -------
// slot words (8B each, parity-doubled): w0 = (maxmind<<32)|(invidx<<17)|tag
//   w1 = (xbits<<32)|tag   w2 = (ybits<<32)|tag   w3 = (zbits<<32)|tag
__global__ void __launch_bounds__(FPS_THREADS, 1) __cluster_dims__(FPS_CTAS, 1, 1)
fps_kernel(const float* __restrict__ pos) {
    __shared__ unsigned long long s_slot[8];        // [parity][word]
    __shared__ unsigned s_val[FPS_WARPS], s_idx[FPS_WARPS];
    __shared__ float s_wx[FPS_WARPS], s_wy[FPS_WARPS], s_wz[FPS_WARPS];
    __shared__ float s_pick[3];

    const int tid  = threadIdx.x;
    const int warp = tid >> 5, lane = tid & 31;
    const int cta  = blockIdx.x;
    const int wbase = (cta * FPS_WARPS + warp) * (FPS_PPT * 32);  // 256 pts per warp

    float X[FPS_PPT], Y[FPS_PPT], Z[FPS_PPT], Mn[FPS_PPT];
    unsigned I[FPS_PPT];
    #pragma unroll
    for (int p = 0; p < FPS_PPT; ++p) {
        int j = wbase + lane + p * 32;
        X[p] = g_bx[j]; Y[p] = g_by[j]; Z[p] = g_bz[j];
        I[p] = (unsigned)g_bidx[j];
        Mn[p] = __int_as_float(0x7f800000);
    }

    // warp bbox over its 256 points (one-time)
    float bxmin = X[0], bxmax = X[0], bymin = Y[0], bymax = Y[0];
    float bzmin = Z[0], bzmax = Z[0];
    #pragma unroll
    for (int p = 1; p < FPS_PPT; ++p) {
        bxmin = fminf(bxmin, X[p]); bxmax = fmaxf(bxmax, X[p]);
        bymin = fminf(bymin, Y[p]); bymax = fmaxf(bymax, Y[p]);
        bzmin = fminf(bzmin, Z[p]); bzmax = fmaxf(bzmax, Z[p]);
    }
    #pragma unroll
    for (int off = 16; off > 0; off >>= 1) {
        bxmin = fminf(bxmin, __shfl_xor_sync(FULLMASK, bxmin, off));
        bxmax = fmaxf(bxmax, __shfl_xor_sync(FULLMASK, bxmax, off));
        bymin = fminf(bymin, __shfl_xor_sync(FULLMASK, bymin, off));
        bymax = fmaxf(bymax, __shfl_xor_sync(FULLMASK, bymax, off));
        bzmin = fminf(bzmin, __shfl_xor_sync(FULLMASK, bzmin, off));
        bzmax = fmaxf(bzmax, __shfl_xor_sync(FULLMASK, bzmax, off));
    }

    float wval = __int_as_float(0x7f800000);   // cached warp max-mind (skip threshold)

    if (tid < 8) s_slot[tid] = 0ull;

    // DSMEM peer word addresses: lane polls word (lane&3) of peer (lane>>2)
    const uint32_t slot_laddr = (uint32_t)__cvta_generic_to_shared(&s_slot[0]);
    uint32_t peer_base = 0;
    if (warp == 0) {
        asm("mapa.shared::cluster.u32 %0, %1, %2;"
            : "=r"(peer_base) : "r"(slot_laddr), "r"(lane >> 2));
    }

    float px = pos[0], py = pos[1], pz = pos[2];   // first pick = index 0
    if (cta == 0 && tid == 0) g_fps_idx[0] = 0;

    asm volatile("barrier.cluster.arrive.aligned;" ::: "memory");
    asm volatile("barrier.cluster.wait.aligned;"   ::: "memory");

    for (int it = 1; it < M_PTS; ++it) {
        // exact-safe lower bound: rn rounding is monotone, so d_lb <= every lane's fp dist
        float dxl = fmaxf(0.f, fmaxf(__fsub_rn(bxmin, px), __fsub_rn(px, bxmax)));
        float dyl = fmaxf(0.f, fmaxf(__fsub_rn(bymin, py), __fsub_rn(py, bymax)));
        float dzl = fmaxf(0.f, fmaxf(__fsub_rn(bzmin, pz), __fsub_rn(pz, bzmax)));
        float dlb = __fadd_rn(__fadd_rn(__fmul_rn(dxl, dxl), __fmul_rn(dyl, dyl)),
                              __fmul_rn(dzl, dzl));

        if (dlb < wval) {                      // warp-uniform branch
            #pragma unroll
            for (int p = 0; p < FPS_PPT; ++p)
                Mn[p] = fminf(Mn[p], dist2s(X[p], Y[p], Z[p], px, py, pz));

            // thread-local argmax, min-orig-idx tie-break
            float bv = Mn[0]; unsigned bi = I[0];
            float bx = X[0], by = Y[0], bz = Z[0];
            #pragma unroll
            for (int p = 1; p < FPS_PPT; ++p) {
                if (Mn[p] > bv || (Mn[p] == bv && I[p] < bi)) {
                    bv = Mn[p]; bi = I[p]; bx = X[p]; by = Y[p]; bz = Z[p];
                }
            }
            unsigned vb   = __float_as_uint(bv);
            unsigned wmax = __reduce_max_sync(FULLMASK, vb);
            unsigned widx = __reduce_min_sync(FULLMASK, (vb == wmax) ? bi : 0xffffffffu);
            wval = __uint_as_float(wmax);
            if (vb == wmax && bi == widx) {    // unique winner lane stores candidate
                s_val[warp] = wmax; s_idx[warp] = widx;
                s_wx[warp] = bx; s_wy[warp] = by; s_wz[warp] = bz;
            }
        }
        // else: cached smem candidate from last update round is still exact
        __syncthreads();   // BAR1: warp candidates published (16 warps)

        if (warp == 0) {
            // CTA reduce over 16 warp winners (lanes 16-31 duplicate lanes 0-15; max unaffected)
            const int wl16 = lane & (FPS_WARPS - 1);
            unsigned v  = s_val[wl16], ix = s_idx[wl16];
            float xw = s_wx[wl16], yw = s_wy[wl16], zw = s_wz[wl16];
            unsigned cmax = __reduce_max_sync(FULLMASK, v);
            unsigned cidx = __reduce_min_sync(FULLMASK, (v == cmax) ? ix : 0xffffffffu);
            int wl = __ffs(__ballot_sync(FULLMASK, v == cmax && ix == cidx)) - 1;
            float cx = __shfl_sync(FULLMASK, xw, wl);
            float cy = __shfl_sync(FULLMASK, yw, wl);
            float cz = __shfl_sync(FULLMASK, zw, wl);

            const unsigned tag = (unsigned)it;          // < 16384
            const int par = it & 1;
            if (lane == 0) {
                unsigned long long k0 = ((unsigned long long)cmax << 32)
                                      | ((unsigned long long)(32767u - cidx) << 17)
                                      | (unsigned long long)tag;
                unsigned long long k1 = ((unsigned long long)__float_as_uint(cx) << 32) | tag;
                unsigned long long k2 = ((unsigned long long)__float_as_uint(cy) << 32) | tag;
                unsigned long long k3 = ((unsigned long long)__float_as_uint(cz) << 32) | tag;
                uint32_t a = slot_laddr + (uint32_t)(par * 32);
                asm volatile("st.relaxed.cluster.shared::cta.b64 [%0], %1;" :: "r"(a),      "l"(k0) : "memory");
                asm volatile("st.relaxed.cluster.shared::cta.b64 [%0], %1;" :: "r"(a + 8),  "l"(k1) : "memory");
                asm volatile("st.relaxed.cluster.shared::cta.b64 [%0], %1;" :: "r"(a + 16), "l"(k2) : "memory");
                asm volatile("st.relaxed.cluster.shared::cta.b64 [%0], %1;" :: "r"(a + 24), "l"(k3) : "memory");
            }

            // pull: lane polls word (lane&3) of peer (lane>>2); every word self-tagged
            const uint32_t pa = peer_base + (uint32_t)(par * 32 + (lane & 3) * 8);
            unsigned long long v64;
            do {
                asm volatile("ld.relaxed.cluster.shared::cluster.b64 %0, [%1];"
                             : "=l"(v64) : "r"(pa) : "memory");
            } while ((unsigned)(v64 & 0x3FFFull) != tag);

            const bool iskey = (lane & 3) == 0;
            unsigned hval = iskey ? (unsigned)(v64 >> 32) : 0u;
            unsigned hmax = __reduce_max_sync(FULLMASK, hval);
            unsigned hinv = __reduce_max_sync(FULLMASK,
                                (iskey && hval == hmax)
                                    ? (unsigned)((v64 >> 17) & 0x7FFFull) : 0u);
            int l0 = __ffs(__ballot_sync(FULLMASK,
                        iskey && hval == hmax
                        && (unsigned)((v64 >> 17) & 0x7FFFull) == hinv)) - 1;
            unsigned hi32 = (unsigned)(v64 >> 32);
            float pkx = __uint_as_float(__shfl_sync(FULLMASK, hi32, l0 + 1));
            float pky = __uint_as_float(__shfl_sync(FULLMASK, hi32, l0 + 2));
            float pkz = __uint_as_float(__shfl_sync(FULLMASK, hi32, l0 + 3));
            if (lane == 0) {
                s_pick[0] = pkx; s_pick[1] = pky; s_pick[2] = pkz;
                if (cta == 0) g_fps_idx[it] = 32767 - (int)hinv;
            }
        }
        __syncthreads();   // BAR2: s_pick published
        px = s_pick[0]; py = s_pick[1]; pz = s_pick[2];
    }

    asm volatile("barrier.cluster.arrive.aligned;" ::: "memory");
    asm volatile("barrier.cluster.wait.aligned;"   ::: "memory");
}

// ---------------- KNN: warp per query, smem-chunked candidate points ----------------
#define KNN_THREADS 256
#define KNN_CHUNK   4096

__global__ void __launch_bounds__(KNN_THREADS) knn_kernel(const float* __restrict__ pos) {
    __shared__ float s_pos[KNN_CHUNK * 3];
    const int tid  = threadIdx.x;
    const int warp = tid >> 5, lane = tid & 31;
    const int m    = blockIdx.x * (KNN_THREADS / 32) + warp;

    const int qidx = g_fps_idx[m];
    const float qx = pos[qidx * 3 + 0];
    const float qy = pos[qidx * 3 + 1];
    const float qz = pos[qidx * 3 + 2];

    unsigned long long bk[KNN_K];
    #pragma unroll
    for (int i = 0; i < KNN_K; ++i) bk[i] = 0xFFFFFFFFFFFFFFFFull;
    unsigned long long worst = 0xFFFFFFFFFFFFFFFFull;
    int ws = 0;

    for (int base = 0; base < N_PTS; base += KNN_CHUNK) {
        __syncthreads();
        for (int i = tid; i < KNN_CHUNK * 3; i += KNN_THREADS)
            s_pos[i] = pos[base * 3 + i];
        __syncthreads();

        for (int j = lane; j < KNN_CHUNK; j += 32) {
            float d = dist2s(qx, qy, qz, s_pos[j * 3], s_pos[j * 3 + 1], s_pos[j * 3 + 2]);
            unsigned long long key = ((unsigned long long)__float_as_uint(d) << 32)
                                   | (unsigned int)(base + j);
            if (key < worst) {
                bk[ws] = key;
                worst = 0ull;
                #pragma unroll
                for (int i = 0; i < KNN_K; ++i)
                    if (bk[i] > worst) { worst = bk[i]; ws = i; }
            }
        }
    }

    for (int r = 0; r < KNN_K; ++r) {
        unsigned long long lm = 0xFFFFFFFFFFFFFFFFull;
        #pragma unroll
        for (int i = 0; i < KNN_K; ++i) if (bk[i] < lm) lm = bk[i];
        unsigned long long w = lm;
        #pragma unroll
        for (int off = 16; off > 0; off >>= 1) {
            unsigned long long o = __shfl_xor_sync(FULLMASK, w, off);
            if (o < w) w = o;
        }
        if (lane == 0) g_nbr[m * KNN_K + r] = (int)(w & 0xFFFFFFFFull);
        if (lm == w) {
            bool rm = false;
            #pragma unroll
            for (int i = 0; i < KNN_K; ++i)
                if (!rm && bk[i] == w) { bk[i] = 0xFFFFFFFFFFFFFFFFull; rm = true; }
        }
    }
}

// ---------------- MLP: h = relu(x @ W + b) ----------------
#define GEMM_THREADS 256
#define GEMM_ROWS    16

__global__ void __launch_bounds__(GEMM_THREADS) mlp_kernel(const float* __restrict__ x,
                                                           const float* __restrict__ W,
                                                           const float* __restrict__ b) {
    __shared__ float sW[CIN * COUT];
    __shared__ float sx[GEMM_ROWS * CIN];
    const int tid  = threadIdx.x;
    const int row0 = blockIdx.x * GEMM_ROWS;

    for (int i = tid; i < CIN * COUT; i += GEMM_THREADS) sW[i] = W[i];
    for (int i = tid; i < GEMM_ROWS * CIN; i += GEMM_THREADS) sx[i] = x[row0 * CIN + i];
    __syncthreads();

    const int c  = tid & (COUT - 1);
    const int rg = tid >> 7;
    float acc[8];
    #pragma unroll
    for (int r = 0; r < 8; ++r) acc[r] = 0.f;

    for (int k = 0; k < CIN; ++k) {
        float wv = sW[k * COUT + c];
        #pragma unroll
        for (int r = 0; r < 8; ++r)
            acc[r] = fmaf(sx[(rg * 8 + r) * CIN + k], wv, acc[r]);
    }
    float bv = b[c];
    #pragma unroll
    for (int r = 0; r < 8; ++r)
        g_h[(row0 + rg * 8 + r) * COUT + c] = fmaxf(acc[r] + bv, 0.f);
}

// ---------------- max over K neighbors ----------------
__global__ void __launch_bounds__(COUT) gather_kernel(float* __restrict__ out) {
    const int m = blockIdx.x;
    const int c = threadIdx.x;
    __shared__ int s_n[KNN_K];
    if (c < KNN_K) s_n[c] = g_nbr[m * KNN_K + c];
    __syncthreads();
    float best = g_h[s_n[0] * COUT + c];
    #pragma unroll
    for (int k = 1; k < KNN_K; ++k)
        best = fmaxf(best, g_h[s_n[k] * COUT + c]);
    out[m * COUT + c] = best;
}

// ---------------- sub_pos + sub_batch ----------------
__global__ void subpos_kernel(const float* __restrict__ pos, float* __restrict__ out) {
    const int m = blockIdx.x * blockDim.x + threadIdx.x;
    if (m < M_PTS) {
        const int idx = g_fps_idx[m];
        float* sp = out + (M_PTS * COUT);
        sp[m * 3 + 0] = pos[idx * 3 + 0];
        sp[m * 3 + 1] = pos[idx * 3 + 1];
        sp[m * 3 + 2] = pos[idx * 3 + 2];
        out[M_PTS * COUT + M_PTS * 3 + m] = 0.0f;   // sub_batch = 0
    }
}

extern "C" void kernel_launch(void* const* d_in, const int* in_sizes, int n_in,
                              void* d_out, int out_size) {
    const float* x   = (const float*)d_in[0];
    const float* pos = (const float*)d_in[1];
    const float* W   = (const float*)d_in[3];
    const float* b   = (const float*)d_in[4];
    float* out = (float*)d_out;

    // order chosen so fps_kernel is launch index 3 (the one ncu captures)
    hist_kernel<<<32, 1024>>>(pos);
    scan_kernel<<<1, 1024>>>();
    scatter_kernel<<<32, 1024>>>(pos);
    fps_kernel<<<FPS_CTAS, FPS_THREADS>>>(pos);
    mlp_kernel<<<N_PTS / GEMM_ROWS, GEMM_THREADS>>>(x, W, b);
    subpos_kernel<<<(M_PTS + 255) / 256, 256>>>(pos, out);
    knn_kernel<<<M_PTS / (KNN_THREADS / 32), KNN_THREADS>>>(pos);
    gather_kernel<<<M_PTS, COUT>>>(out);
}

// round 11
// speedup vs baseline: 4.8423x; 1.1320x over previous
#include <cuda_runtime.h>
#include <cstdint>

#define N_PTS 32768
#define M_PTS 8192
#define CIN   64
#define COUT  128
#define KNN_K 16

#define FPS_CTAS    8
#define FPS_THREADS 1024
#define FPS_PPT     4      // 8*1024*4 = 32768
#define FULLMASK    0xffffffffu

#define N_CHUNKS    256    // 256 chunks x 128 binned points

// ---------------- scratch (device globals; no allocation allowed) ----------------
__device__ int   g_fps_idx[M_PTS];
__device__ int   g_nbr[M_PTS * KNN_K];
__device__ float g_h[N_PTS * COUT];      // relu(xW+b), 16 MB
// binning scratch
__device__ int   g_cellcnt[4096];        // zero-init; scan re-zeroes after reading
__device__ int   g_celloff[4096];
__device__ int   g_cellstart[4096];      // immutable copy of cell starts (for knn)
__device__ float g_bx[N_PTS], g_by[N_PTS], g_bz[N_PTS];
__device__ int   g_bidx[N_PTS];
__device__ float4 g_cboxA[N_CHUNKS];     // chunk bbox min (x,y,z,-)
__device__ float4 g_cboxB[N_CHUNKS];     // chunk bbox max (x,y,z,-)

// strict non-FMA fp32 distance: matches XLA mul -> reduce-add (rel_err==0 verified)
__device__ __forceinline__ float dist2s(float x, float y, float z,
                                        float px, float py, float pz) {
    float dx = __fsub_rn(x, px);
    float dy = __fsub_rn(y, py);
    float dz = __fsub_rn(z, pz);
    return __fadd_rn(__fadd_rn(__fmul_rn(dx, dx), __fmul_rn(dy, dy)), __fmul_rn(dz, dz));
}

// exact-safe lower bound to a bbox: rn rounding is monotone -> lb <= every fp distance
__device__ __forceinline__ float bbox_lb(float px, float py, float pz,
                                         float xmin, float xmax, float ymin,
                                         float ymax, float zmin, float zmax) {
    float dxl = fmaxf(0.f, fmaxf(__fsub_rn(xmin, px), __fsub_rn(px, xmax)));
    float dyl = fmaxf(0.f, fmaxf(__fsub_rn(ymin, py), __fsub_rn(py, ymax)));
    float dzl = fmaxf(0.f, fmaxf(__fsub_rn(zmin, pz), __fsub_rn(pz, zmax)));
    return __fadd_rn(__fadd_rn(__fmul_rn(dxl, dxl), __fmul_rn(dyl, dyl)),
                     __fmul_rn(dzl, dzl));
}

// ---------------- binning: 16^3 Morton grid ----------------
__device__ __forceinline__ int expand3(int v) {
    return (v & 1) | ((v & 2) << 2) | ((v & 4) << 4) | ((v & 8) << 6);
}
__device__ __forceinline__ int cell_of(float x, float y, float z) {
    int cx = min(15, max(0, (int)floorf((x + 4.0f) * 2.0f)));
    int cy = min(15, max(0, (int)floorf((y + 4.0f) * 2.0f)));
    int cz = min(15, max(0, (int)floorf((z + 4.0f) * 2.0f)));
    return expand3(cx) | (expand3(cy) << 1) | (expand3(cz) << 2);
}

__global__ void hist_kernel(const float* __restrict__ pos) {
    int i = blockIdx.x * blockDim.x + threadIdx.x;
    if (i < N_PTS)
        atomicAdd(&g_cellcnt[cell_of(pos[i*3], pos[i*3+1], pos[i*3+2])], 1);
}

// scan ALSO re-zeroes g_cellcnt (clean replays) and saves immutable starts
__global__ void __launch_bounds__(1024) scan_kernel() {
    __shared__ int s_w[32];
    const int tid = threadIdx.x, lane = tid & 31, w = tid >> 5;
    int v0 = g_cellcnt[tid*4+0], v1 = g_cellcnt[tid*4+1];
    int v2 = g_cellcnt[tid*4+2], v3 = g_cellcnt[tid*4+3];
    g_cellcnt[tid*4+0] = 0; g_cellcnt[tid*4+1] = 0;
    g_cellcnt[tid*4+2] = 0; g_cellcnt[tid*4+3] = 0;
    int local = v0 + v1 + v2 + v3;
    int x = local;
    #pragma unroll
    for (int off = 1; off < 32; off <<= 1) {
        int y = __shfl_up_sync(FULLMASK, x, off);
        if (lane >= off) x += y;
    }
    if (lane == 31) s_w[w] = x;
    __syncthreads();
    if (w == 0) {
        int y = s_w[lane];
        #pragma unroll
        for (int off = 1; off < 32; off <<= 1) {
            int z = __shfl_up_sync(FULLMASK, y, off);
            if (lane >= off) y += z;
        }
        s_w[lane] = y;
    }
    __syncthreads();
    int exc = x - local + (w > 0 ? s_w[w-1] : 0);
    int o0 = exc, o1 = exc + v0, o2 = exc + v0 + v1, o3 = exc + v0 + v1 + v2;
    g_celloff[tid*4+0] = o0;  g_cellstart[tid*4+0] = o0;
    g_celloff[tid*4+1] = o1;  g_cellstart[tid*4+1] = o1;
    g_celloff[tid*4+2] = o2;  g_cellstart[tid*4+2] = o2;
    g_celloff[tid*4+3] = o3;  g_cellstart[tid*4+3] = o3;
}

__global__ void scatter_kernel(const float* __restrict__ pos) {
    int i = blockIdx.x * blockDim.x + threadIdx.x;
    if (i < N_PTS) {
        float x = pos[i*3], y = pos[i*3+1], z = pos[i*3+2];
        int slot = atomicAdd(&g_celloff[cell_of(x, y, z)], 1);
        g_bx[slot] = x; g_by[slot] = y; g_bz[slot] = z; g_bidx[slot] = i;
    }
}

// ---------------- chunk bboxes: one warp per 128-pt chunk ----------------
__global__ void __launch_bounds__(256) cbox_kernel() {
    const int warp = threadIdx.x >> 5, lane = threadIdx.x & 31;
    const int c = blockIdx.x * 8 + warp;
    const int base = c * 128;
    float xmin, xmax, ymin, ymax, zmin, zmax;
    {
        float x0 = g_bx[base + lane],      y0 = g_by[base + lane],      z0 = g_bz[base + lane];
        float x1 = g_bx[base + lane + 32], y1 = g_by[base + lane + 32], z1 = g_bz[base + lane + 32];
        float x2 = g_bx[base + lane + 64], y2 = g_by[base + lane + 64], z2 = g_bz[base + lane + 64];
        float x3 = g_bx[base + lane + 96], y3 = g_by[base + lane + 96], z3 = g_bz[base + lane + 96];
        xmin = fminf(fminf(x0, x1), fminf(x2, x3));
        xmax = fmaxf(fmaxf(x0, x1), fmaxf(x2, x3));
        ymin = fminf(fminf(y0, y1), fminf(y2, y3));
        ymax = fmaxf(fmaxf(y0, y1), fmaxf(y2, y3));
        zmin = fminf(fminf(z0, z1), fminf(z2, z3));
        zmax = fmaxf(fmaxf(z0, z1), fmaxf(z2, z3));
    }
    #pragma unroll
    for (int off = 16; off > 0; off >>= 1) {
        xmin = fminf(xmin, __shfl_xor_sync(FULLMASK, xmin, off));
        xmax = fmaxf(xmax, __shfl_xor_sync(FULLMASK, xmax, off));
        ymin = fminf(ymin, __shfl_xor_sync(FULLMASK, ymin, off));
        ymax = fmaxf(ymax, __shfl_xor_sync(FULLMASK, ymax, off));
        zmin = fminf(zmin, __shfl_xor_sync(FULLMASK, zmin, off));
        zmax = fmaxf(zmax, __shfl_xor_sync(FULLMASK, zmax, off));
    }
    if (lane == 0) {
        g_cboxA[c] = make_float4(xmin, ymin, zmin, 0.f);
        g_cboxB[c] = make_float4(xmax, ymax, zmax, 0.f);
    }
}

// ---------------- FPS: R3-exact (8 CTAs x 1024 thr, warp bbox, pull exchange) ------
// slot words (8B each, parity-doubled): w0 = (maxmind<<32)|(invidx<<17)|tag
//   w1 = (xbits<<32)|tag   w2 = (ybits<<32)|tag   w3 = (zbits<<32)|tag
__global__ void __launch_bounds__(FPS_THREADS, 1) __cluster_dims__(FPS_CTAS, 1, 1)
fps_kernel(const float* __restrict__ pos) {
    __shared__ unsigned long long s_slot[8];        // [parity][word]
    __shared__ unsigned s_val[32], s_idx[32];
    __shared__ float s_wx[32], s_wy[32], s_wz[32];
    __shared__ float s_pick[3];

    const int tid  = threadIdx.x;
    const int warp = tid >> 5, lane = tid & 31;
    const int cta  = blockIdx.x;
    const int wbase = (cta * 32 + warp) * 128;      // this warp's 128 binned points

    float X[FPS_PPT], Y[FPS_PPT], Z[FPS_PPT], Mn[FPS_PPT];
    unsigned I[FPS_PPT];
    #pragma unroll
    for (int p = 0; p < FPS_PPT; ++p) {
        int j = wbase + lane + p * 32;
        X[p] = g_bx[j]; Y[p] = g_by[j]; Z[p] = g_bz[j];
        I[p] = (unsigned)g_bidx[j];
        Mn[p] = __int_as_float(0x7f800000);
    }

    // warp bbox over its 128 points (one-time)
    float bxmin = fminf(fminf(X[0], X[1]), fminf(X[2], X[3]));
    float bxmax = fmaxf(fmaxf(X[0], X[1]), fmaxf(X[2], X[3]));
    float bymin = fminf(fminf(Y[0], Y[1]), fminf(Y[2], Y[3]));
    float bymax = fmaxf(fmaxf(Y[0], Y[1]), fmaxf(Y[2], Y[3]));
    float bzmin = fminf(fminf(Z[0], Z[1]), fminf(Z[2], Z[3]));
    float bzmax = fmaxf(fmaxf(Z[0], Z[1]), fmaxf(Z[2], Z[3]));
    #pragma unroll
    for (int off = 16; off > 0; off >>= 1) {
        bxmin = fminf(bxmin, __shfl_xor_sync(FULLMASK, bxmin, off));
        bxmax = fmaxf(bxmax, __shfl_xor_sync(FULLMASK, bxmax, off));
        bymin = fminf(bymin, __shfl_xor_sync(FULLMASK, bymin, off));
        bymax = fmaxf(bymax, __shfl_xor_sync(FULLMASK, bymax, off));
        bzmin = fminf(bzmin, __shfl_xor_sync(FULLMASK, bzmin, off));
        bzmax = fmaxf(bzmax, __shfl_xor_sync(FULLMASK, bzmax, off));
    }

    float wval = __int_as_float(0x7f800000);   // cached warp max-mind (skip threshold)

    if (tid < 8) s_slot[tid] = 0ull;

    // DSMEM peer word addresses: lane polls word (lane&3) of peer (lane>>2)
    const uint32_t slot_laddr = (uint32_t)__cvta_generic_to_shared(&s_slot[0]);
    uint32_t peer_base = 0;
    if (warp == 0) {
        asm("mapa.shared::cluster.u32 %0, %1, %2;"
            : "=r"(peer_base) : "r"(slot_laddr), "r"(lane >> 2));
    }

    float px = pos[0], py = pos[1], pz = pos[2];   // first pick = index 0
    if (cta == 0 && tid == 0) g_fps_idx[0] = 0;

    asm volatile("barrier.cluster.arrive.aligned;" ::: "memory");
    asm volatile("barrier.cluster.wait.aligned;"   ::: "memory");

    for (int it = 1; it < M_PTS; ++it) {
        float dlb = bbox_lb(px, py, pz, bxmin, bxmax, bymin, bymax, bzmin, bzmax);

        if (dlb < wval) {                      // warp-uniform branch
            #pragma unroll
            for (int p = 0; p < FPS_PPT; ++p)
                Mn[p] = fminf(Mn[p], dist2s(X[p], Y[p], Z[p], px, py, pz));

            // thread-local argmax, min-orig-idx tie-break
            float bv = Mn[0]; unsigned bi = I[0];
            float bx = X[0], by = Y[0], bz = Z[0];
            #pragma unroll
            for (int p = 1; p < FPS_PPT; ++p) {
                if (Mn[p] > bv || (Mn[p] == bv && I[p] < bi)) {
                    bv = Mn[p]; bi = I[p]; bx = X[p]; by = Y[p]; bz = Z[p];
                }
            }
            unsigned vb   = __float_as_uint(bv);
            unsigned wmax = __reduce_max_sync(FULLMASK, vb);
            unsigned widx = __reduce_min_sync(FULLMASK, (vb == wmax) ? bi : 0xffffffffu);
            wval = __uint_as_float(wmax);
            if (vb == wmax && bi == widx) {    // unique winner lane stores candidate
                s_val[warp] = wmax; s_idx[warp] = widx;
                s_wx[warp] = bx; s_wy[warp] = by; s_wz[warp] = bz;
            }
        }
        // else: cached smem candidate from last update round is still exact
        __syncthreads();   // BAR1: warp candidates published

        if (warp == 0) {
            unsigned v  = s_val[lane], ix = s_idx[lane];
            float xw = s_wx[lane], yw = s_wy[lane], zw = s_wz[lane];
            unsigned cmax = __reduce_max_sync(FULLMASK, v);
            unsigned cidx = __reduce_min_sync(FULLMASK, (v == cmax) ? ix : 0xffffffffu);
            int wl = __ffs(__ballot_sync(FULLMASK, v == cmax && ix == cidx)) - 1;
            float cx = __shfl_sync(FULLMASK, xw, wl);
            float cy = __shfl_sync(FULLMASK, yw, wl);
            float cz = __shfl_sync(FULLMASK, zw, wl);

            const unsigned tag = (unsigned)it;          // < 16384
            const int par = it & 1;
            if (lane == 0) {
                unsigned long long k0 = ((unsigned long long)cmax << 32)
                                      | ((unsigned long long)(32767u - cidx) << 17)
                                      | (unsigned long long)tag;
                unsigned long long k1 = ((unsigned long long)__float_as_uint(cx) << 32) | tag;
                unsigned long long k2 = ((unsigned long long)__float_as_uint(cy) << 32) | tag;
                unsigned long long k3 = ((unsigned long long)__float_as_uint(cz) << 32) | tag;
                uint32_t a = slot_laddr + (uint32_t)(par * 32);
                asm volatile("st.relaxed.cluster.shared::cta.b64 [%0], %1;" :: "r"(a),      "l"(k0) : "memory");
                asm volatile("st.relaxed.cluster.shared::cta.b64 [%0], %1;" :: "r"(a + 8),  "l"(k1) : "memory");
                asm volatile("st.relaxed.cluster.shared::cta.b64 [%0], %1;" :: "r"(a + 16), "l"(k2) : "memory");
                asm volatile("st.relaxed.cluster.shared::cta.b64 [%0], %1;" :: "r"(a + 24), "l"(k3) : "memory");
            }

            // pull: lane polls word (lane&3) of peer (lane>>2); every word self-tagged
            const uint32_t pa = peer_base + (uint32_t)(par * 32 + (lane & 3) * 8);
            unsigned long long v64;
            do {
                asm volatile("ld.relaxed.cluster.shared::cluster.b64 %0, [%1];"
                             : "=l"(v64) : "r"(pa) : "memory");
            } while ((unsigned)(v64 & 0x3FFFull) != tag);

            const bool iskey = (lane & 3) == 0;
            unsigned hval = iskey ? (unsigned)(v64 >> 32) : 0u;
            unsigned hmax = __reduce_max_sync(FULLMASK, hval);
            unsigned hinv = __reduce_max_sync(FULLMASK,
                                (iskey && hval == hmax)
                                    ? (unsigned)((v64 >> 17) & 0x7FFFull) : 0u);
            int l0 = __ffs(__ballot_sync(FULLMASK,
                        iskey && hval == hmax
                        && (unsigned)((v64 >> 17) & 0x7FFFull) == hinv)) - 1;
            unsigned hi32 = (unsigned)(v64 >> 32);
            float pkx = __uint_as_float(__shfl_sync(FULLMASK, hi32, l0 + 1));
            float pky = __uint_as_float(__shfl_sync(FULLMASK, hi32, l0 + 2));
            float pkz = __uint_as_float(__shfl_sync(FULLMASK, hi32, l0 + 3));
            if (lane == 0) {
                s_pick[0] = pkx; s_pick[1] = pky; s_pick[2] = pkz;
                if (cta == 0) g_fps_idx[it] = 32767 - (int)hinv;
            }
        }
        __syncthreads();   // BAR2: s_pick published
        px = s_pick[0]; py = s_pick[1]; pz = s_pick[2];
    }

    asm volatile("barrier.cluster.arrive.aligned;" ::: "memory");
    asm volatile("barrier.cluster.wait.aligned;"   ::: "memory");
}

// ---------------- KNN: warp per query, chunked branch-and-bound over bins ----------
__global__ void __launch_bounds__(256) knn_kernel(const float* __restrict__ pos) {
    const int warp = threadIdx.x >> 5, lane = threadIdx.x & 31;
    const int m    = blockIdx.x * 8 + warp;

    const int qidx = g_fps_idx[m];
    const float qx = pos[qidx * 3 + 0];
    const float qy = pos[qidx * 3 + 1];
    const float qz = pos[qidx * 3 + 2];

    // start at the chunk containing the query's own cell -> worst tightens fast
    const int sc = g_cellstart[cell_of(qx, qy, qz)] >> 7;

    // sentinel: +inf distance bits, max idx; any real key is smaller
    const unsigned long long SENT = ((unsigned long long)0x7F800000u << 32) | 0xFFFFFFFFull;
    unsigned long long bk[KNN_K];
    #pragma unroll
    for (int i = 0; i < KNN_K; ++i) bk[i] = SENT;
    unsigned long long worst = SENT;
    float worst_d = __int_as_float(0x7f800000);   // +inf
    int ws = 0;

    for (int t = 0; t < N_CHUNKS; ++t) {
        const int c = (sc + t) & (N_CHUNKS - 1);
        float4 lo = g_cboxA[c];
        float4 hi = g_cboxB[c];
        float dlb = bbox_lb(qx, qy, qz, lo.x, hi.x, lo.y, hi.y, lo.z, hi.z);
        if (dlb > worst_d) continue;      // exact-safe prune (strict: ties never lost)

        const int base = c * 128 + lane;
        #pragma unroll
        for (int p = 0; p < 4; ++p) {
            const int j = base + p * 32;
            float d = dist2s(g_bx[j], g_by[j], g_bz[j], qx, qy, qz);
            if (d <= worst_d) {
                unsigned long long key = ((unsigned long long)__float_as_uint(d) << 32)
                                       | (unsigned)g_bidx[j];
                if (key < worst) {        // lexicographic (d, idx): stable top_k
                    bk[ws] = key;
                    worst = 0ull;
                    #pragma unroll
                    for (int i = 0; i < KNN_K; ++i)
                        if (bk[i] > worst) { worst = bk[i]; ws = i; }
                    worst_d = __uint_as_float((unsigned)(worst >> 32));
                }
            }
        }
    }

    // merge 32 lanes' top-16 -> global top-16 (keys unique: idx in low bits)
    for (int r = 0; r < KNN_K; ++r) {
        unsigned long long lm = 0xFFFFFFFFFFFFFFFFull;
        #pragma unroll
        for (int i = 0; i < KNN_K; ++i) if (bk[i] < lm) lm = bk[i];
        unsigned long long w = lm;
        #pragma unroll
        for (int off = 16; off > 0; off >>= 1) {
            unsigned long long o = __shfl_xor_sync(FULLMASK, w, off);
            if (o < w) w = o;
        }
        if (lane == 0) g_nbr[m * KNN_K + r] = (int)(w & 0xFFFFFFFFull);
        if (lm == w) {
            bool rm = false;
            #pragma unroll
            for (int i = 0; i < KNN_K; ++i)
                if (!rm && bk[i] == w) { bk[i] = 0xFFFFFFFFFFFFFFFFull; rm = true; }
        }
    }
}

// ---------------- MLP: h = relu(x @ W + b) ----------------
#define GEMM_THREADS 256
#define GEMM_ROWS    16

__global__ void __launch_bounds__(GEMM_THREADS) mlp_kernel(const float* __restrict__ x,
                                                           const float* __restrict__ W,
                                                           const float* __restrict__ b) {
    __shared__ float sW[CIN * COUT];
    __shared__ float sx[GEMM_ROWS * CIN];
    const int tid  = threadIdx.x;
    const int row0 = blockIdx.x * GEMM_ROWS;

    for (int i = tid; i < CIN * COUT; i += GEMM_THREADS) sW[i] = W[i];
    for (int i = tid; i < GEMM_ROWS * CIN; i += GEMM_THREADS) sx[i] = x[row0 * CIN + i];
    __syncthreads();

    const int c  = tid & (COUT - 1);
    const int rg = tid >> 7;
    float acc[8];
    #pragma unroll
    for (int r = 0; r < 8; ++r) acc[r] = 0.f;

    for (int k = 0; k < CIN; ++k) {
        float wv = sW[k * COUT + c];
        #pragma unroll
        for (int r = 0; r < 8; ++r)
            acc[r] = fmaf(sx[(rg * 8 + r) * CIN + k], wv, acc[r]);
    }
    float bv = b[c];
    #pragma unroll
    for (int r = 0; r < 8; ++r)
        g_h[(row0 + rg * 8 + r) * COUT + c] = fmaxf(acc[r] + bv, 0.f);
}

// ---------------- max over K neighbors ----------------
__global__ void __launch_bounds__(COUT) gather_kernel(float* __restrict__ out) {
    const int m = blockIdx.x;
    const int c = threadIdx.x;
    __shared__ int s_n[KNN_K];
    if (c < KNN_K) s_n[c] = g_nbr[m * KNN_K + c];
    __syncthreads();
    float best = g_h[s_n[0] * COUT + c];
    #pragma unroll
    for (int k = 1; k < KNN_K; ++k)
        best = fmaxf(best, g_h[s_n[k] * COUT + c]);
    out[m * COUT + c] = best;
}

// ---------------- sub_pos + sub_batch ----------------
__global__ void subpos_kernel(const float* __restrict__ pos, float* __restrict__ out) {
    const int m = blockIdx.x * blockDim.x + threadIdx.x;
    if (m < M_PTS) {
        const int idx = g_fps_idx[m];
        float* sp = out + (M_PTS * COUT);
        sp[m * 3 + 0] = pos[idx * 3 + 0];
        sp[m * 3 + 1] = pos[idx * 3 + 1];
        sp[m * 3 + 2] = pos[idx * 3 + 2];
        out[M_PTS * COUT + M_PTS * 3 + m] = 0.0f;   // sub_batch = 0
    }
}

extern "C" void kernel_launch(void* const* d_in, const int* in_sizes, int n_in,
                              void* d_out, int out_size) {
    const float* x   = (const float*)d_in[0];
    const float* pos = (const float*)d_in[1];
    const float* W   = (const float*)d_in[3];
    const float* b   = (const float*)d_in[4];
    float* out = (float*)d_out;

    // order chosen so fps_kernel is launch index 3 (the one ncu captures)
    hist_kernel<<<32, 1024>>>(pos);
    scan_kernel<<<1, 1024>>>();
    scatter_kernel<<<32, 1024>>>(pos);
    fps_kernel<<<FPS_CTAS, FPS_THREADS>>>(pos);
    cbox_kernel<<<32, 256>>>();
    mlp_kernel<<<N_PTS / GEMM_ROWS, GEMM_THREADS>>>(x, W, b);
    subpos_kernel<<<(M_PTS + 255) / 256, 256>>>(pos, out);
    knn_kernel<<<M_PTS / 8, 256>>>(pos);
    gather_kernel<<<M_PTS, COUT>>>(out);
}